// round 1
// baseline (speedup 1.0000x reference)
#include <cuda_runtime.h>
#include <math_constants.h>

// Problem constants
#define D_MODEL 1024
#define NHEAD   16
#define DEPTH   64
#define BATCH   2
#define SEQ     2048
#define M_TOTAL (BATCH*SEQ)   // 4096

// Scratch (device globals — no allocation allowed in kernel_launch)
__device__ float g_q[(size_t)BATCH*NHEAD*SEQ*DEPTH];   // q in [b,h,s,d]
__device__ float g_ao[(size_t)M_TOTAL*D_MODEL];        // attention output, [b,s,h*64+d]

// ---------------------------------------------------------------------------
// SGEMM: C[M,N] = A[M,K] @ B[K,N] + bias[N]
// BM=BN=128, BK=16, 256 threads, 8x8 fragments, global->reg prefetch.
// QKV=1: scatter epilogue (q -> out0 scratch [b,h,s,d], k/v -> present)
// QKV=0: plain row-major epilogue into out0 [M,N]
// ---------------------------------------------------------------------------
template<int QKV>
__global__ __launch_bounds__(256)
void sgemm128(const float* __restrict__ A, const float* __restrict__ Bm,
              const float* __restrict__ bias, float* __restrict__ out0,
              float* __restrict__ present, int N, int K)
{
    __shared__ float As[16][128];
    __shared__ float Bs[16][128];

    const int tid = threadIdx.x;
    const int tx = tid & 15;
    const int ty = tid >> 4;
    const int m0 = blockIdx.y * 128;
    const int n0 = blockIdx.x * 128;

    float acc[8][8];
#pragma unroll
    for (int i = 0; i < 8; i++)
#pragma unroll
        for (int j = 0; j < 8; j++) acc[i][j] = 0.f;

    // A loader: 512 float4 per tile (128 rows x 16 cols). This thread: rows
    // arow0 and arow0+64, col group akc.
    const int arow0 = tid >> 2;
    const int akc   = (tid & 3) << 2;
    // B loader: rows brow0 and brow0+8, cols bnc..bnc+3
    const int brow0 = tid >> 5;
    const int bnc   = (tid & 31) << 2;

    const float* Aptr = A  + (size_t)(m0 + arow0) * K + akc;
    const float* Bptr = Bm + (size_t)brow0 * N + n0 + bnc;

    float4 aR0, aR1, bR0, bR1;
    aR0 = *(const float4*)(Aptr);
    aR1 = *(const float4*)(Aptr + (size_t)64 * K);
    bR0 = *(const float4*)(Bptr);
    bR1 = *(const float4*)(Bptr + (size_t)8 * N);

    // store tile 0
    {
        const float* a0 = (const float*)&aR0;
        const float* a1 = (const float*)&aR1;
#pragma unroll
        for (int e = 0; e < 4; e++) {
            As[akc + e][arow0]      = a0[e];
            As[akc + e][arow0 + 64] = a1[e];
        }
        *(float4*)&Bs[brow0][bnc]     = bR0;
        *(float4*)&Bs[brow0 + 8][bnc] = bR1;
    }
    __syncthreads();

    for (int kt = 16; kt <= K; kt += 16) {
        const bool more = (kt < K);
        if (more) {
            aR0 = *(const float4*)(Aptr + kt);
            aR1 = *(const float4*)(Aptr + kt + (size_t)64 * K);
            bR0 = *(const float4*)(Bptr + (size_t)kt * N);
            bR1 = *(const float4*)(Bptr + (size_t)(kt + 8) * N);
        }
#pragma unroll
        for (int kk = 0; kk < 16; kk++) {
            float a[8], b[8];
            *(float4*)&a[0] = *(const float4*)&As[kk][ty * 8];
            *(float4*)&a[4] = *(const float4*)&As[kk][ty * 8 + 4];
            *(float4*)&b[0] = *(const float4*)&Bs[kk][tx * 8];
            *(float4*)&b[4] = *(const float4*)&Bs[kk][tx * 8 + 4];
#pragma unroll
            for (int i = 0; i < 8; i++)
#pragma unroll
                for (int j = 0; j < 8; j++)
                    acc[i][j] += a[i] * b[j];
        }
        __syncthreads();
        if (more) {
            const float* a0 = (const float*)&aR0;
            const float* a1 = (const float*)&aR1;
#pragma unroll
            for (int e = 0; e < 4; e++) {
                As[akc + e][arow0]      = a0[e];
                As[akc + e][arow0 + 64] = a1[e];
            }
            *(float4*)&Bs[brow0][bnc]     = bR0;
            *(float4*)&Bs[brow0 + 8][bnc] = bR1;
            __syncthreads();
        }
    }

    // Epilogue
#pragma unroll
    for (int i = 0; i < 8; i++) {
        const int m = m0 + ty * 8 + i;
#pragma unroll
        for (int jg = 0; jg < 2; jg++) {
            const int n = n0 + tx * 8 + jg * 4;
            float4 v;
            v.x = acc[i][jg * 4 + 0] + bias[n + 0];
            v.y = acc[i][jg * 4 + 1] + bias[n + 1];
            v.z = acc[i][jg * 4 + 2] + bias[n + 2];
            v.w = acc[i][jg * 4 + 3] + bias[n + 3];
            if (QKV == 0) {
                *(float4*)&out0[(size_t)m * N + n] = v;
            } else {
                const int bidx = m >> 11;        // / SEQ
                const int s    = m & (SEQ - 1);
                const int tsr  = n >> 10;        // 0=q 1=k 2=v
                const int nn   = n & (D_MODEL - 1);
                const int h    = nn >> 6;
                const int d    = nn & 63;
                float* dst;
                if (tsr == 0) {
                    dst = out0 + ((((size_t)bidx * NHEAD + h) * SEQ + s) * DEPTH + d);
                } else {
                    dst = present + ((((size_t)(bidx * 2 + (tsr - 1)) * NHEAD + h) * SEQ + s) * DEPTH + d);
                }
                *(float4*)dst = v;
            }
        }
    }
}

// ---------------------------------------------------------------------------
// Flash attention: one CTA per (q-tile 64, head, batch). D=64.
// Online softmax, exact causal (skipped tiles underflow to 0 identically to
// the reference's additive -1e9 mask).
// ---------------------------------------------------------------------------
__global__ __launch_bounds__(256)
void attn_kernel(const float* __restrict__ q, const float* __restrict__ present,
                 float* __restrict__ ao)
{
    extern __shared__ float smem[];
    float* Qt = smem;            // [d][q]  (transposed, pre-scaled)
    float* Kt = smem + 4096;     // [d][k]  (transposed)
    float* Vs = smem + 8192;     // [k][d]
    float* Pt = smem + 12288;    // [k][q]  (transposed P)

    const int tid = threadIdx.x;
    const int tx = tid & 15;
    const int ty = tid >> 4;
    const int qt = blockIdx.x;
    const int h  = blockIdx.y;
    const int b  = blockIdx.z;
    const int q0 = qt * 64;

    // Load Q tile, transpose + scale by 1/sqrt(64)
    {
        const float* qg = q + (((size_t)(b * NHEAD + h)) * SEQ + q0) * DEPTH;
        const int r  = tid >> 2;
        const int dc = (tid & 3) << 4;
#pragma unroll
        for (int e = 0; e < 4; e++) {
            float4 v = *(const float4*)(qg + r * 64 + dc + e * 4);
            Qt[(dc + e * 4 + 0) * 64 + r] = v.x * 0.125f;
            Qt[(dc + e * 4 + 1) * 64 + r] = v.y * 0.125f;
            Qt[(dc + e * 4 + 2) * 64 + r] = v.z * 0.125f;
            Qt[(dc + e * 4 + 3) * 64 + r] = v.w * 0.125f;
        }
    }

    float mrow[4], lrow[4], o[4][4];
#pragma unroll
    for (int i = 0; i < 4; i++) {
        mrow[i] = -CUDART_INF_F;
        lrow[i] = 0.f;
#pragma unroll
        for (int j = 0; j < 4; j++) o[i][j] = 0.f;
    }

    const float* kg = present + ((size_t)((b * 2 + 0) * NHEAD + h)) * SEQ * DEPTH;
    const float* vg = present + ((size_t)((b * 2 + 1) * NHEAD + h)) * SEQ * DEPTH;

    for (int kt = 0; kt <= qt; kt++) {
        const int k0 = kt * 64;
        // Load K (transposed) and V (natural)
        {
            const int r  = tid >> 2;
            const int dc = (tid & 3) << 4;
            const float* kp = kg + (size_t)(k0 + r) * 64 + dc;
            const float* vp = vg + (size_t)(k0 + r) * 64 + dc;
#pragma unroll
            for (int e = 0; e < 4; e++) {
                float4 kv = *(const float4*)(kp + e * 4);
                Kt[(dc + e * 4 + 0) * 64 + r] = kv.x;
                Kt[(dc + e * 4 + 1) * 64 + r] = kv.y;
                Kt[(dc + e * 4 + 2) * 64 + r] = kv.z;
                Kt[(dc + e * 4 + 3) * 64 + r] = kv.w;
                *(float4*)&Vs[r * 64 + dc + e * 4] = *(const float4*)(vp + e * 4);
            }
        }
        __syncthreads();

        // S = Q @ K^T   (16 outputs per thread)
        float sfrag[4][4];
#pragma unroll
        for (int i = 0; i < 4; i++)
#pragma unroll
            for (int j = 0; j < 4; j++) sfrag[i][j] = 0.f;

#pragma unroll 8
        for (int d = 0; d < 64; d++) {
            float4 aq = *(const float4*)(Qt + d * 64 + ty * 4);
            float4 bk = *(const float4*)(Kt + d * 64 + tx * 4);
            const float* av = (const float*)&aq;
            const float* bv = (const float*)&bk;
#pragma unroll
            for (int i = 0; i < 4; i++)
#pragma unroll
                for (int j = 0; j < 4; j++)
                    sfrag[i][j] += av[i] * bv[j];
        }

        if (kt == qt) {
            // causal mask on the diagonal tile
#pragma unroll
            for (int i = 0; i < 4; i++) {
                const int qi = q0 + ty * 4 + i;
#pragma unroll
                for (int j = 0; j < 4; j++) {
                    const int ki = k0 + tx * 4 + j;
                    if (ki > qi) sfrag[i][j] = -1e9f;
                }
            }
        }

        // Online softmax update
        float p[4][4];
#pragma unroll
        for (int i = 0; i < 4; i++) {
            float mx = fmaxf(fmaxf(sfrag[i][0], sfrag[i][1]),
                             fmaxf(sfrag[i][2], sfrag[i][3]));
#pragma unroll
            for (int off = 8; off >= 1; off >>= 1)
                mx = fmaxf(mx, __shfl_xor_sync(0xffffffffu, mx, off));
            const float newm  = fmaxf(mrow[i], mx);
            const float alpha = __expf(mrow[i] - newm);
            float sum = 0.f;
#pragma unroll
            for (int j = 0; j < 4; j++) {
                p[i][j] = __expf(sfrag[i][j] - newm);
                sum += p[i][j];
            }
#pragma unroll
            for (int off = 8; off >= 1; off >>= 1)
                sum += __shfl_xor_sync(0xffffffffu, sum, off);
            lrow[i] = lrow[i] * alpha + sum;
            mrow[i] = newm;
#pragma unroll
            for (int j = 0; j < 4; j++) o[i][j] *= alpha;
        }

        // Stage P transposed: Pt[k][q]
#pragma unroll
        for (int j = 0; j < 4; j++) {
            float4 v;
            v.x = p[0][j]; v.y = p[1][j]; v.z = p[2][j]; v.w = p[3][j];
            *(float4*)&Pt[(tx * 4 + j) * 64 + ty * 4] = v;
        }
        __syncthreads();

        // O += P @ V
#pragma unroll 8
        for (int k = 0; k < 64; k++) {
            float4 ap = *(const float4*)(Pt + k * 64 + ty * 4);
            float4 vv = *(const float4*)(Vs + k * 64 + tx * 4);
            const float* av = (const float*)&ap;
            const float* bv = (const float*)&vv;
#pragma unroll
            for (int i = 0; i < 4; i++)
#pragma unroll
                for (int j = 0; j < 4; j++)
                    o[i][j] += av[i] * bv[j];
        }
        __syncthreads();
    }

    // Normalize + write merged-head layout [b][s][h*64+d]
#pragma unroll
    for (int i = 0; i < 4; i++) {
        const float inv = 1.f / lrow[i];
        float4 v;
        v.x = o[i][0] * inv; v.y = o[i][1] * inv;
        v.z = o[i][2] * inv; v.w = o[i][3] * inv;
        const size_t row = (size_t)b * SEQ + (q0 + ty * 4 + i);
        *(float4*)&ao[row * D_MODEL + h * 64 + tx * 4] = v;
    }
}

// ---------------------------------------------------------------------------
extern "C" void kernel_launch(void* const* d_in, const int* in_sizes, int n_in,
                              void* d_out, int out_size)
{
    const float* x      = (const float*)d_in[0];
    // d_in[1] = mask (analytically causal; not needed)
    const float* w_attn = (const float*)d_in[2];
    const float* b_attn = (const float*)d_in[3];
    const float* w_proj = (const float*)d_in[4];
    const float* b_proj = (const float*)d_in[5];

    float* out     = (float*)d_out;                                  // [B,S,D_MODEL]
    float* present = out + (size_t)M_TOTAL * D_MODEL;                // [B,2,H,S,D]

    float* gq;  cudaGetSymbolAddress((void**)&gq,  g_q);
    float* gao; cudaGetSymbolAddress((void**)&gao, g_ao);

    // 1) QKV GEMM with scatter epilogue
    {
        dim3 grid(3 * D_MODEL / 128, M_TOTAL / 128);
        sgemm128<1><<<grid, 256>>>(x, w_attn, b_attn, gq, present, 3 * D_MODEL, D_MODEL);
    }

    // 2) Flash attention
    {
        static bool attr_set = false;
        if (!attr_set) {
            cudaFuncSetAttribute(attn_kernel,
                                 cudaFuncAttributeMaxDynamicSharedMemorySize,
                                 64 * 1024);
            attr_set = true;
        }
        dim3 grid(SEQ / 64, NHEAD, BATCH);
        attn_kernel<<<grid, 256, 64 * 1024>>>(gq, present, gao);
    }

    // 3) Output projection
    {
        dim3 grid(D_MODEL / 128, M_TOTAL / 128);
        sgemm128<0><<<grid, 256>>>(gao, w_proj, b_proj, out, nullptr, D_MODEL, D_MODEL);
    }
}

// round 3
// speedup vs baseline: 1.2198x; 1.2198x over previous
#include <cuda_runtime.h>
#include <cuda_bf16.h>
#include <math_constants.h>
#include <cstdint>

// Problem constants
#define D_MODEL 1024
#define NHEAD   16
#define DEPTH   64
#define BATCH   2
#define SEQ     2048
#define M_TOTAL (BATCH*SEQ)   // 4096
#define GK      3072          // split-bf16 K'' = 3*1024

// ---------------------------------------------------------------------------
// Scratch (device globals — no allocation allowed)
// ---------------------------------------------------------------------------
__device__ float g_q [(size_t)BATCH*NHEAD*SEQ*DEPTH];     // q in [b,h,s,d]
__device__ float g_ao[(size_t)M_TOTAL*D_MODEL];           // attn out [b,s,h*64+d]
__device__ __nv_bfloat16 g_Ax  [(size_t)M_TOTAL*GK];      // x split  [M, 3072]
__device__ __nv_bfloat16 g_Aao [(size_t)M_TOTAL*GK];      // ao split [M, 3072]
__device__ __nv_bfloat16 g_Bqkv[(size_t)3*D_MODEL*GK];    // w_attn^T split [3072, 3072]
__device__ __nv_bfloat16 g_Bprj[(size_t)D_MODEL*GK];      // w_proj^T split [1024, 3072]

// ---------------------------------------------------------------------------
// Helpers
// ---------------------------------------------------------------------------
__device__ __forceinline__ uint32_t smem_u32(const void* p) {
    uint32_t a;
    asm("{ .reg .u64 t; cvta.to.shared.u64 t, %1; cvt.u32.u64 %0, t; }" : "=r"(a) : "l"(p));
    return a;
}
__device__ __forceinline__ void cp_async16(uint32_t saddr, const void* gptr) {
    asm volatile("cp.async.cg.shared.global [%0], [%1], 16;" :: "r"(saddr), "l"(gptr));
}
#define CP_COMMIT() asm volatile("cp.async.commit_group;" ::: "memory")
#define CP_WAIT(n)  asm volatile("cp.async.wait_group %0;" :: "n"(n) : "memory")

__device__ __forceinline__ void ldmx4(uint32_t addr, uint32_t& r0, uint32_t& r1,
                                      uint32_t& r2, uint32_t& r3) {
    asm volatile("ldmatrix.sync.aligned.m8n8.x4.shared.b16 {%0,%1,%2,%3}, [%4];"
                 : "=r"(r0), "=r"(r1), "=r"(r2), "=r"(r3) : "r"(addr));
}
__device__ __forceinline__ void mma_bf16(float c[4], uint32_t a0, uint32_t a1,
                                         uint32_t a2, uint32_t a3,
                                         uint32_t b0, uint32_t b1) {
    asm volatile("mma.sync.aligned.m16n8k16.row.col.f32.bf16.bf16.f32 "
                 "{%0,%1,%2,%3}, {%4,%5,%6,%7}, {%8,%9}, {%0,%1,%2,%3};"
                 : "+f"(c[0]), "+f"(c[1]), "+f"(c[2]), "+f"(c[3])
                 : "r"(a0), "r"(a1), "r"(a2), "r"(a3), "r"(b0), "r"(b1));
}

// FMA-pipe exp2 (degree-6 Taylor of 2^f on [0,1); rel err < 3e-6).
// Input clamped so the exponent bit-trick stays in range; t<=0 expected.
__device__ __forceinline__ float exp2_poly(float t) {
    t = fmaxf(t, -125.0f);
    float n = floorf(t);
    float f = t - n;
    float p = 1.5403530393381608e-4f;
    p = fmaf(p, f, 1.3333558146428443e-3f);
    p = fmaf(p, f, 9.6181291076284770e-3f);
    p = fmaf(p, f, 5.5504108664821580e-2f);
    p = fmaf(p, f, 2.4022650695910070e-1f);
    p = fmaf(p, f, 6.9314718055994530e-1f);
    p = fmaf(p, f, 1.0f);
    return p * __int_as_float(((int)n + 127) << 23);
}

// ---------------------------------------------------------------------------
// Prep: x[M,1024] fp32 -> A''[M,3072] bf16 segments (hi, hi, lo)
// ---------------------------------------------------------------------------
__global__ __launch_bounds__(256)
void conv_a_kernel(const float* __restrict__ X, __nv_bfloat16* __restrict__ Ad) {
    int i = blockIdx.x * blockDim.x + threadIdx.x;     // over M*256 float4s
    if (i >= M_TOTAL * 256) return;
    int m  = i >> 8;
    int kq = (i & 255) << 2;
    float4 v = ((const float4*)X)[i];
    union { __nv_bfloat16 h[4]; uint2 u; } hi, lo;
    hi.h[0] = __float2bfloat16(v.x); lo.h[0] = __float2bfloat16(v.x - __bfloat162float(hi.h[0]));
    hi.h[1] = __float2bfloat16(v.y); lo.h[1] = __float2bfloat16(v.y - __bfloat162float(hi.h[1]));
    hi.h[2] = __float2bfloat16(v.z); lo.h[2] = __float2bfloat16(v.z - __bfloat162float(hi.h[2]));
    hi.h[3] = __float2bfloat16(v.w); lo.h[3] = __float2bfloat16(v.w - __bfloat162float(hi.h[3]));
    size_t base = (size_t)m * GK + kq;
    *(uint2*)(Ad + base)        = hi.u;
    *(uint2*)(Ad + base + 1024) = hi.u;
    *(uint2*)(Ad + base + 2048) = lo.u;
}

// ---------------------------------------------------------------------------
// Prep: w[1024,N] fp32 -> B''[N,3072] bf16 (transposed; segments hi, lo, hi)
// ---------------------------------------------------------------------------
__global__ __launch_bounds__(256)
void conv_w_kernel(const float* __restrict__ W, __nv_bfloat16* __restrict__ Bd, int N) {
    __shared__ float t[32][33];
    const int k0 = blockIdx.y * 32, n0 = blockIdx.x * 32;
    for (int r = threadIdx.y; r < 32; r += 8)
        t[r][threadIdx.x] = W[(size_t)(k0 + r) * N + n0 + threadIdx.x];
    __syncthreads();
    for (int r = threadIdx.y; r < 32; r += 8) {
        const int n = n0 + r, k = k0 + threadIdx.x;
        float v = t[threadIdx.x][r];
        __nv_bfloat16 h  = __float2bfloat16(v);
        __nv_bfloat16 lo = __float2bfloat16(v - __bfloat162float(h));
        __nv_bfloat16* row = Bd + (size_t)n * GK;
        row[k]        = h;
        row[1024 + k] = lo;
        row[2048 + k] = h;
    }
}

// ---------------------------------------------------------------------------
// mma.sync bf16 GEMM: D[M,N] = A''[M,GK] @ B''[N,GK]^T + bias
// 128x128 tile, BK=64 bf16 (128B rows, xor-swizzled), 3-stage cp.async.
// 8 warps: 2x4 grid, warp tile 64x32. m16n8k16 fragments via ldmatrix.
// QKV=1: scatter q->out0 [b,h,s,d], k/v->present. QKV=0: row-major out0.
// ---------------------------------------------------------------------------
#define NKIT (GK/64)          // 48
#define STG_BYTES 32768       // (128 A rows + 128 B rows) * 128B
#define SMEM_MMA (3*STG_BYTES)

template<int QKV>
__global__ __launch_bounds__(256, 1)
void gemm_mma(const __nv_bfloat16* __restrict__ A, const __nv_bfloat16* __restrict__ B,
              const float* __restrict__ bias, float* __restrict__ out0,
              float* __restrict__ present, int N)
{
    extern __shared__ __align__(128) char smem[];
    const uint32_t sbase = smem_u32(smem);

    const int tid  = threadIdx.x;
    const int lane = tid & 31, wid = tid >> 5;
    const int m0 = blockIdx.y * 128, n0 = blockIdx.x * 128;
    const int wm0 = (wid >> 2) * 64;      // warp m offset within tile
    const int wn0 = (wid & 3) * 32;       // warp n offset within tile

    // Loader: 2 threads per row, 4 x 16B each. Swizzle: col16 ^= (row & 7).
    const int lrow = tid >> 1;
    const int lc0  = (tid & 1) * 4;
    const __nv_bfloat16* aG = A + (size_t)(m0 + lrow) * GK;
    const __nv_bfloat16* bG = B + (size_t)(n0 + lrow) * GK;
    uint32_t wOff[4];
#pragma unroll
    for (int i = 0; i < 4; i++)
        wOff[i] = (uint32_t)lrow * 128 + (uint32_t)(((lc0 + i) ^ (lrow & 7)) << 4);

    float c[4][4][4];
#pragma unroll
    for (int mi = 0; mi < 4; mi++)
#pragma unroll
        for (int ni = 0; ni < 4; ni++)
#pragma unroll
            for (int e = 0; e < 4; e++) c[mi][ni][e] = 0.f;

    auto load_stage = [&](int st, int kt) {
        const uint32_t s0 = sbase + st * STG_BYTES;
        const __nv_bfloat16* ag = aG + kt * 64;
        const __nv_bfloat16* bg = bG + kt * 64;
#pragma unroll
        for (int i = 0; i < 4; i++) {
            cp_async16(s0 + wOff[i],         ag + (lc0 + i) * 8);
            cp_async16(s0 + 16384 + wOff[i], bg + (lc0 + i) * 8);
        }
    };

    auto compute = [&](int st) {
        const uint32_t sA = sbase + st * STG_BYTES;
        const uint32_t sB = sA + 16384;
#pragma unroll
        for (int ks = 0; ks < 4; ks++) {
            uint32_t a[4][4];
#pragma unroll
            for (int mi = 0; mi < 4; mi++) {
                const int r  = wm0 + mi * 16 + (lane & 15);
                const int cc = ks * 2 + (lane >> 4);
                ldmx4(sA + r * 128 + (((cc ^ (r & 7))) << 4),
                      a[mi][0], a[mi][1], a[mi][2], a[mi][3]);
            }
            uint32_t b[4][2];
#pragma unroll
            for (int np = 0; np < 2; np++) {
                const int r  = wn0 + np * 16 + (lane & 7) + ((lane >> 4) << 3);
                const int cc = ks * 2 + ((lane >> 3) & 1);
                uint32_t r0, r1, r2, r3;
                ldmx4(sB + r * 128 + (((cc ^ (r & 7))) << 4), r0, r1, r2, r3);
                b[np * 2][0] = r0; b[np * 2][1] = r1;
                b[np * 2 + 1][0] = r2; b[np * 2 + 1][1] = r3;
            }
#pragma unroll
            for (int mi = 0; mi < 4; mi++)
#pragma unroll
                for (int ni = 0; ni < 4; ni++)
                    mma_bf16(c[mi][ni], a[mi][0], a[mi][1], a[mi][2], a[mi][3],
                             b[ni][0], b[ni][1]);
        }
    };

    load_stage(0, 0); CP_COMMIT();
    load_stage(1, 1); CP_COMMIT();

    for (int kt = 0; kt < NKIT; kt++) {
        CP_WAIT(1);
        __syncthreads();
        if (kt + 2 < NKIT) load_stage((kt + 2) % 3, kt + 2);
        CP_COMMIT();
        compute(kt % 3);
    }

    // Epilogue: c[mi][ni] = rows {gr, gr+8}, cols {tc*2, tc*2+1}
    const int gr = lane >> 2, tc = lane & 3;
#pragma unroll
    for (int mi = 0; mi < 4; mi++) {
#pragma unroll
        for (int rr = 0; rr < 2; rr++) {
            const int m = m0 + wm0 + mi * 16 + gr + rr * 8;
            const int bidx = m >> 11, s = m & (SEQ - 1);
#pragma unroll
            for (int ni = 0; ni < 4; ni++) {
                const int n = n0 + wn0 + ni * 8 + tc * 2;
                float2 bb = *(const float2*)(bias + n);
                float2 v;
                v.x = c[mi][ni][rr * 2 + 0] + bb.x;
                v.y = c[mi][ni][rr * 2 + 1] + bb.y;
                if (QKV == 0) {
                    *(float2*)&out0[(size_t)m * N + n] = v;
                } else {
                    const int tsr = n >> 10;           // 0=q 1=k 2=v
                    const int nn  = n & (D_MODEL - 1);
                    const int h   = nn >> 6, d = nn & 63;
                    float* dst = (tsr == 0)
                        ? out0    + ((((size_t)bidx * NHEAD + h) * SEQ + s) * DEPTH + d)
                        : present + ((((size_t)(bidx * 2 + (tsr - 1)) * NHEAD + h) * SEQ + s) * DEPTH + d);
                    *(float2*)dst = v;
                }
            }
        }
    }
}

// ---------------------------------------------------------------------------
// Flash attention: one CTA per (q-tile 64, head, batch). fp32, poly exp2.
// Q pre-scaled by 0.125*log2(e): scores live in log2 domain.
// ---------------------------------------------------------------------------
#define QSCALE (0.125f * 1.4426950408889634f)

__global__ __launch_bounds__(256)
void attn_kernel(const float* __restrict__ q, const float* __restrict__ present,
                 float* __restrict__ ao)
{
    extern __shared__ float fsm[];
    float* Qt = fsm;            // [d][q]
    float* Kt = fsm + 4096;     // [d][k]
    float* Vs = fsm + 8192;     // [k][d]
    float* Pt = fsm + 12288;    // [k][q]

    const int tid = threadIdx.x;
    const int tx = tid & 15;
    const int ty = tid >> 4;
    const int qt = blockIdx.x;
    const int h  = blockIdx.y;
    const int b  = blockIdx.z;
    const int q0 = qt * 64;

    {
        const float* qg = q + (((size_t)(b * NHEAD + h)) * SEQ + q0) * DEPTH;
        const int r  = tid >> 2;
        const int dc = (tid & 3) << 4;
#pragma unroll
        for (int e = 0; e < 4; e++) {
            float4 v = *(const float4*)(qg + r * 64 + dc + e * 4);
            Qt[(dc + e * 4 + 0) * 64 + r] = v.x * QSCALE;
            Qt[(dc + e * 4 + 1) * 64 + r] = v.y * QSCALE;
            Qt[(dc + e * 4 + 2) * 64 + r] = v.z * QSCALE;
            Qt[(dc + e * 4 + 3) * 64 + r] = v.w * QSCALE;
        }
    }

    float mrow[4], lrow[4], o[4][4];
#pragma unroll
    for (int i = 0; i < 4; i++) {
        mrow[i] = -CUDART_INF_F;
        lrow[i] = 0.f;
#pragma unroll
        for (int j = 0; j < 4; j++) o[i][j] = 0.f;
    }

    const float* kg = present + ((size_t)((b * 2 + 0) * NHEAD + h)) * SEQ * DEPTH;
    const float* vg = present + ((size_t)((b * 2 + 1) * NHEAD + h)) * SEQ * DEPTH;

    for (int kt = 0; kt <= qt; kt++) {
        const int k0 = kt * 64;
        {
            const int r  = tid >> 2;
            const int dc = (tid & 3) << 4;
            const float* kp = kg + (size_t)(k0 + r) * 64 + dc;
            const float* vp = vg + (size_t)(k0 + r) * 64 + dc;
#pragma unroll
            for (int e = 0; e < 4; e++) {
                float4 kv = *(const float4*)(kp + e * 4);
                Kt[(dc + e * 4 + 0) * 64 + r] = kv.x;
                Kt[(dc + e * 4 + 1) * 64 + r] = kv.y;
                Kt[(dc + e * 4 + 2) * 64 + r] = kv.z;
                Kt[(dc + e * 4 + 3) * 64 + r] = kv.w;
                *(float4*)&Vs[r * 64 + dc + e * 4] = *(const float4*)(vp + e * 4);
            }
        }
        __syncthreads();

        float sfrag[4][4];
#pragma unroll
        for (int i = 0; i < 4; i++)
#pragma unroll
            for (int j = 0; j < 4; j++) sfrag[i][j] = 0.f;

#pragma unroll 8
        for (int d = 0; d < 64; d++) {
            float4 aq = *(const float4*)(Qt + d * 64 + ty * 4);
            float4 bk = *(const float4*)(Kt + d * 64 + tx * 4);
            const float* av = (const float*)&aq;
            const float* bv = (const float*)&bk;
#pragma unroll
            for (int i = 0; i < 4; i++)
#pragma unroll
                for (int j = 0; j < 4; j++)
                    sfrag[i][j] += av[i] * bv[j];
        }

        if (kt == qt) {
#pragma unroll
            for (int i = 0; i < 4; i++) {
                const int qi = q0 + ty * 4 + i;
#pragma unroll
                for (int j = 0; j < 4; j++) {
                    const int ki = k0 + tx * 4 + j;
                    if (ki > qi) sfrag[i][j] = -1e9f;
                }
            }
        }

        float p[4][4];
#pragma unroll
        for (int i = 0; i < 4; i++) {
            float mx = fmaxf(fmaxf(sfrag[i][0], sfrag[i][1]),
                             fmaxf(sfrag[i][2], sfrag[i][3]));
#pragma unroll
            for (int off = 8; off >= 1; off >>= 1)
                mx = fmaxf(mx, __shfl_xor_sync(0xffffffffu, mx, off));
            const float newm  = fmaxf(mrow[i], mx);
            const float alpha = exp2_poly(mrow[i] - newm);
            float sum = 0.f;
#pragma unroll
            for (int j = 0; j < 4; j++) {
                p[i][j] = exp2_poly(sfrag[i][j] - newm);
                sum += p[i][j];
            }
#pragma unroll
            for (int off = 8; off >= 1; off >>= 1)
                sum += __shfl_xor_sync(0xffffffffu, sum, off);
            lrow[i] = lrow[i] * alpha + sum;
            mrow[i] = newm;
#pragma unroll
            for (int j = 0; j < 4; j++) o[i][j] *= alpha;
        }

#pragma unroll
        for (int j = 0; j < 4; j++) {
            float4 v;
            v.x = p[0][j]; v.y = p[1][j]; v.z = p[2][j]; v.w = p[3][j];
            *(float4*)&Pt[(tx * 4 + j) * 64 + ty * 4] = v;
        }
        __syncthreads();

#pragma unroll 8
        for (int k = 0; k < 64; k++) {
            float4 ap = *(const float4*)(Pt + k * 64 + ty * 4);
            float4 vv = *(const float4*)(Vs + k * 64 + tx * 4);
            const float* av = (const float*)&ap;
            const float* bv = (const float*)&vv;
#pragma unroll
            for (int i = 0; i < 4; i++)
#pragma unroll
                for (int j = 0; j < 4; j++)
                    o[i][j] += av[i] * bv[j];
        }
        __syncthreads();
    }

#pragma unroll
    for (int i = 0; i < 4; i++) {
        const float inv = 1.f / lrow[i];
        float4 v;
        v.x = o[i][0] * inv; v.y = o[i][1] * inv;
        v.z = o[i][2] * inv; v.w = o[i][3] * inv;
        const size_t row = (size_t)b * SEQ + (q0 + ty * 4 + i);
        *(float4*)&ao[row * D_MODEL + h * 64 + tx * 4] = v;
    }
}

// ---------------------------------------------------------------------------
extern "C" void kernel_launch(void* const* d_in, const int* in_sizes, int n_in,
                              void* d_out, int out_size)
{
    const float* x      = (const float*)d_in[0];
    const float* w_attn = (const float*)d_in[2];
    const float* b_attn = (const float*)d_in[3];
    const float* w_proj = (const float*)d_in[4];
    const float* b_proj = (const float*)d_in[5];

    float* out     = (float*)d_out;
    float* present = out + (size_t)M_TOTAL * D_MODEL;

    float* gq;  cudaGetSymbolAddress((void**)&gq,  g_q);
    float* gao; cudaGetSymbolAddress((void**)&gao, g_ao);
    __nv_bfloat16 *gAx, *gAao, *gBq, *gBp;
    cudaGetSymbolAddress((void**)&gAx,  g_Ax);
    cudaGetSymbolAddress((void**)&gAao, g_Aao);
    cudaGetSymbolAddress((void**)&gBq,  g_Bqkv);
    cudaGetSymbolAddress((void**)&gBp,  g_Bprj);

    static bool attr_set = false;
    if (!attr_set) {
        cudaFuncSetAttribute(attn_kernel, cudaFuncAttributeMaxDynamicSharedMemorySize, 64 * 1024);
        cudaFuncSetAttribute(gemm_mma<1>, cudaFuncAttributeMaxDynamicSharedMemorySize, SMEM_MMA);
        cudaFuncSetAttribute(gemm_mma<0>, cudaFuncAttributeMaxDynamicSharedMemorySize, SMEM_MMA);
        attr_set = true;
    }

    // Prep: split-bf16 operands
    conv_a_kernel<<<(M_TOTAL * 256 + 255) / 256, 256>>>(x, gAx);
    conv_w_kernel<<<dim3(3 * D_MODEL / 32, D_MODEL / 32), dim3(32, 8)>>>(w_attn, gBq, 3 * D_MODEL);
    conv_w_kernel<<<dim3(D_MODEL / 32, D_MODEL / 32), dim3(32, 8)>>>(w_proj, gBp, D_MODEL);

    // QKV GEMM (tensor cores, mma.sync) with scatter epilogue
    gemm_mma<1><<<dim3(3 * D_MODEL / 128, M_TOTAL / 128), 256, SMEM_MMA>>>(
        gAx, gBq, b_attn, gq, present, 3 * D_MODEL);

    // Flash attention (fp32 + FMA-pipe exp2)
    attn_kernel<<<dim3(SEQ / 64, NHEAD, BATCH), 256, 64 * 1024>>>(gq, present, gao);

    // Proj GEMM
    conv_a_kernel<<<(M_TOTAL * 256 + 255) / 256, 256>>>(gao, gAao);
    gemm_mma<0><<<dim3(D_MODEL / 128, M_TOTAL / 128), 256, SMEM_MMA>>>(
        gAao, gBp, b_proj, out, nullptr, D_MODEL);
}

// round 4
// speedup vs baseline: 2.2427x; 1.8386x over previous
#include <cuda_runtime.h>
#include <cuda_bf16.h>
#include <math_constants.h>
#include <cstdint>

// Problem constants
#define D_MODEL 1024
#define NHEAD   16
#define DEPTH   64
#define BATCH   2
#define SEQ     2048
#define M_TOTAL (BATCH*SEQ)   // 4096
#define GK      3072          // split-bf16 K'' = 3*1024
#define QSCALE  (0.125f * 1.4426950408889634f)   // 1/sqrt(64) * log2(e)

// ---------------------------------------------------------------------------
// Scratch (device globals — no allocation allowed)
// ---------------------------------------------------------------------------
__device__ __nv_bfloat16 g_qs [(size_t)BATCH*NHEAD*SEQ*128];  // q split [b,h,s,(hi64|lo64)], pre-scaled
__device__ __nv_bfloat16 g_ks [(size_t)BATCH*NHEAD*SEQ*128];  // k split
__device__ __nv_bfloat16 g_vs [(size_t)BATCH*NHEAD*SEQ*128];  // v split
__device__ __nv_bfloat16 g_Ax [(size_t)M_TOTAL*GK];           // x split  [M, 3072]
__device__ __nv_bfloat16 g_Aao[(size_t)M_TOTAL*GK];           // attn-out split [M, 3072]
__device__ __nv_bfloat16 g_Bqkv[(size_t)3*D_MODEL*GK];        // w_attn^T split
__device__ __nv_bfloat16 g_Bprj[(size_t)D_MODEL*GK];          // w_proj^T split

// ---------------------------------------------------------------------------
// Helpers
// ---------------------------------------------------------------------------
__device__ __forceinline__ uint32_t smem_u32(const void* p) {
    uint32_t a;
    asm("{ .reg .u64 t; cvta.to.shared.u64 t, %1; cvt.u32.u64 %0, t; }" : "=r"(a) : "l"(p));
    return a;
}
__device__ __forceinline__ void cp_async16(uint32_t saddr, const void* gptr) {
    asm volatile("cp.async.cg.shared.global [%0], [%1], 16;" :: "r"(saddr), "l"(gptr));
}
#define CP_COMMIT() asm volatile("cp.async.commit_group;" ::: "memory")
#define CP_WAIT(n)  asm volatile("cp.async.wait_group %0;" :: "n"(n) : "memory")

__device__ __forceinline__ void ldmx4(uint32_t addr, uint32_t& r0, uint32_t& r1,
                                      uint32_t& r2, uint32_t& r3) {
    asm volatile("ldmatrix.sync.aligned.m8n8.x4.shared.b16 {%0,%1,%2,%3}, [%4];"
                 : "=r"(r0), "=r"(r1), "=r"(r2), "=r"(r3) : "r"(addr));
}
__device__ __forceinline__ void ldmx4t(uint32_t addr, uint32_t& r0, uint32_t& r1,
                                       uint32_t& r2, uint32_t& r3) {
    asm volatile("ldmatrix.sync.aligned.m8n8.x4.trans.shared.b16 {%0,%1,%2,%3}, [%4];"
                 : "=r"(r0), "=r"(r1), "=r"(r2), "=r"(r3) : "r"(addr));
}
__device__ __forceinline__ void mma_bf16(float c[4], uint32_t a0, uint32_t a1,
                                         uint32_t a2, uint32_t a3,
                                         uint32_t b0, uint32_t b1) {
    asm volatile("mma.sync.aligned.m16n8k16.row.col.f32.bf16.bf16.f32 "
                 "{%0,%1,%2,%3}, {%4,%5,%6,%7}, {%8,%9}, {%0,%1,%2,%3};"
                 : "+f"(c[0]), "+f"(c[1]), "+f"(c[2]), "+f"(c[3])
                 : "r"(a0), "r"(a1), "r"(a2), "r"(a3), "r"(b0), "r"(b1));
}

// FMA-pipe exp2 (degree-6; rel err < 3e-6). Inputs expected <= 0.
__device__ __forceinline__ float exp2_poly(float t) {
    t = fmaxf(t, -125.0f);
    float n = floorf(t);
    float f = t - n;
    float p = 1.5403530393381608e-4f;
    p = fmaf(p, f, 1.3333558146428443e-3f);
    p = fmaf(p, f, 9.6181291076284770e-3f);
    p = fmaf(p, f, 5.5504108664821580e-2f);
    p = fmaf(p, f, 2.4022650695910070e-1f);
    p = fmaf(p, f, 6.9314718055994530e-1f);
    p = fmaf(p, f, 1.0f);
    return p * __int_as_float(((int)n + 127) << 23);
}

__device__ __forceinline__ uint32_t pack_hi(float a, float b, float& ha, float& hb) {
    __nv_bfloat162 hh = __floats2bfloat162_rn(a, b);
    ha = __bfloat162float(hh.x);
    hb = __bfloat162float(hh.y);
    return *(uint32_t*)&hh;
}
__device__ __forceinline__ uint32_t pack_bf2(float a, float b) {
    __nv_bfloat162 hh = __floats2bfloat162_rn(a, b);
    return *(uint32_t*)&hh;
}

// ---------------------------------------------------------------------------
// Prep: x[M,1024] fp32 -> A''[M,3072] bf16 segments (hi, hi, lo)
// ---------------------------------------------------------------------------
__global__ __launch_bounds__(256)
void conv_a_kernel(const float* __restrict__ X, __nv_bfloat16* __restrict__ Ad) {
    int i = blockIdx.x * blockDim.x + threadIdx.x;
    if (i >= M_TOTAL * 256) return;
    int m  = i >> 8;
    int kq = (i & 255) << 2;
    float4 v = ((const float4*)X)[i];
    union { __nv_bfloat16 h[4]; uint2 u; } hi, lo;
    hi.h[0] = __float2bfloat16(v.x); lo.h[0] = __float2bfloat16(v.x - __bfloat162float(hi.h[0]));
    hi.h[1] = __float2bfloat16(v.y); lo.h[1] = __float2bfloat16(v.y - __bfloat162float(hi.h[1]));
    hi.h[2] = __float2bfloat16(v.z); lo.h[2] = __float2bfloat16(v.z - __bfloat162float(hi.h[2]));
    hi.h[3] = __float2bfloat16(v.w); lo.h[3] = __float2bfloat16(v.w - __bfloat162float(hi.h[3]));
    size_t base = (size_t)m * GK + kq;
    *(uint2*)(Ad + base)        = hi.u;
    *(uint2*)(Ad + base + 1024) = hi.u;
    *(uint2*)(Ad + base + 2048) = lo.u;
}

// ---------------------------------------------------------------------------
// Prep: w[1024,N] fp32 -> B''[N,3072] bf16 (transposed; segments hi, lo, hi)
// ---------------------------------------------------------------------------
__global__ __launch_bounds__(256)
void conv_w_kernel(const float* __restrict__ W, __nv_bfloat16* __restrict__ Bd, int N) {
    __shared__ float t[32][33];
    const int k0 = blockIdx.y * 32, n0 = blockIdx.x * 32;
    for (int r = threadIdx.y; r < 32; r += 8)
        t[r][threadIdx.x] = W[(size_t)(k0 + r) * N + n0 + threadIdx.x];
    __syncthreads();
    for (int r = threadIdx.y; r < 32; r += 8) {
        const int n = n0 + r, k = k0 + threadIdx.x;
        float v = t[threadIdx.x][r];
        __nv_bfloat16 h  = __float2bfloat16(v);
        __nv_bfloat16 lo = __float2bfloat16(v - __bfloat162float(h));
        __nv_bfloat16* row = Bd + (size_t)n * GK;
        row[k]        = h;
        row[1024 + k] = lo;
        row[2048 + k] = h;
    }
}

// ---------------------------------------------------------------------------
// mma.sync bf16 GEMM: D[M,N] = A''[M,GK] @ B''[N,GK]^T + bias
// QKV=1: q -> g_qs (scaled, split bf16), k/v -> present fp32 + g_ks/g_vs bf16.
// QKV=0: row-major fp32 out0.
// ---------------------------------------------------------------------------
#define NKIT (GK/64)          // 48
#define STG_BYTES 32768
#define SMEM_MMA (3*STG_BYTES)

template<int QKV>
__global__ __launch_bounds__(256, 1)
void gemm_mma(const __nv_bfloat16* __restrict__ A, const __nv_bfloat16* __restrict__ B,
              const float* __restrict__ bias, float* __restrict__ out0,
              float* __restrict__ present, int N,
              __nv_bfloat16* __restrict__ qsp, __nv_bfloat16* __restrict__ ksp,
              __nv_bfloat16* __restrict__ vsp)
{
    extern __shared__ __align__(128) char smem[];
    const uint32_t sbase = smem_u32(smem);

    const int tid  = threadIdx.x;
    const int lane = tid & 31, wid = tid >> 5;
    const int m0 = blockIdx.y * 128, n0 = blockIdx.x * 128;
    const int wm0 = (wid >> 2) * 64;
    const int wn0 = (wid & 3) * 32;

    const int lrow = tid >> 1;
    const int lc0  = (tid & 1) * 4;
    const __nv_bfloat16* aG = A + (size_t)(m0 + lrow) * GK;
    const __nv_bfloat16* bG = B + (size_t)(n0 + lrow) * GK;
    uint32_t wOff[4];
#pragma unroll
    for (int i = 0; i < 4; i++)
        wOff[i] = (uint32_t)lrow * 128 + (uint32_t)(((lc0 + i) ^ (lrow & 7)) << 4);

    float c[4][4][4];
#pragma unroll
    for (int mi = 0; mi < 4; mi++)
#pragma unroll
        for (int ni = 0; ni < 4; ni++)
#pragma unroll
            for (int e = 0; e < 4; e++) c[mi][ni][e] = 0.f;

    auto load_stage = [&](int st, int kt) {
        const uint32_t s0 = sbase + st * STG_BYTES;
        const __nv_bfloat16* ag = aG + kt * 64;
        const __nv_bfloat16* bg = bG + kt * 64;
#pragma unroll
        for (int i = 0; i < 4; i++) {
            cp_async16(s0 + wOff[i],         ag + (lc0 + i) * 8);
            cp_async16(s0 + 16384 + wOff[i], bg + (lc0 + i) * 8);
        }
    };

    auto compute = [&](int st) {
        const uint32_t sA = sbase + st * STG_BYTES;
        const uint32_t sB = sA + 16384;
#pragma unroll
        for (int ks = 0; ks < 4; ks++) {
            uint32_t a[4][4];
#pragma unroll
            for (int mi = 0; mi < 4; mi++) {
                const int r  = wm0 + mi * 16 + (lane & 15);
                const int cc = ks * 2 + (lane >> 4);
                ldmx4(sA + r * 128 + (((cc ^ (r & 7))) << 4),
                      a[mi][0], a[mi][1], a[mi][2], a[mi][3]);
            }
            uint32_t b[4][2];
#pragma unroll
            for (int np = 0; np < 2; np++) {
                const int r  = wn0 + np * 16 + (lane & 7) + ((lane >> 4) << 3);
                const int cc = ks * 2 + ((lane >> 3) & 1);
                uint32_t r0, r1, r2, r3;
                ldmx4(sB + r * 128 + (((cc ^ (r & 7))) << 4), r0, r1, r2, r3);
                b[np * 2][0] = r0; b[np * 2][1] = r1;
                b[np * 2 + 1][0] = r2; b[np * 2 + 1][1] = r3;
            }
#pragma unroll
            for (int mi = 0; mi < 4; mi++)
#pragma unroll
                for (int ni = 0; ni < 4; ni++)
                    mma_bf16(c[mi][ni], a[mi][0], a[mi][1], a[mi][2], a[mi][3],
                             b[ni][0], b[ni][1]);
        }
    };

    load_stage(0, 0); CP_COMMIT();
    load_stage(1, 1); CP_COMMIT();

    for (int kt = 0; kt < NKIT; kt++) {
        CP_WAIT(1);
        __syncthreads();
        if (kt + 2 < NKIT) load_stage((kt + 2) % 3, kt + 2);
        CP_COMMIT();
        compute(kt % 3);
    }

    const int gr = lane >> 2, tc = lane & 3;
#pragma unroll
    for (int mi = 0; mi < 4; mi++) {
#pragma unroll
        for (int rr = 0; rr < 2; rr++) {
            const int m = m0 + wm0 + mi * 16 + gr + rr * 8;
            const int bidx = m >> 11, s = m & (SEQ - 1);
#pragma unroll
            for (int ni = 0; ni < 4; ni++) {
                const int n = n0 + wn0 + ni * 8 + tc * 2;
                float2 bb = *(const float2*)(bias + n);
                float2 v;
                v.x = c[mi][ni][rr * 2 + 0] + bb.x;
                v.y = c[mi][ni][rr * 2 + 1] + bb.y;
                if (QKV == 0) {
                    *(float2*)&out0[(size_t)m * N + n] = v;
                } else {
                    const int tsr = n >> 10;           // 0=q 1=k 2=v
                    const int nn  = n & (D_MODEL - 1);
                    const int h   = nn >> 6, d = nn & 63;
                    const size_t rowi = ((size_t)bidx * NHEAD + h) * SEQ + s;
                    if (tsr == 0) {
                        float q0v = v.x * QSCALE, q1v = v.y * QSCALE;
                        float h0, h1;
                        uint32_t hh = pack_hi(q0v, q1v, h0, h1);
                        uint32_t ll = pack_bf2(q0v - h0, q1v - h1);
                        uint32_t* qrow = (uint32_t*)(qsp + rowi * 128);
                        qrow[d >> 1]        = hh;
                        qrow[32 + (d >> 1)] = ll;
                    } else {
                        float* dst = present +
                            ((((size_t)(bidx * 2 + (tsr - 1)) * NHEAD + h) * SEQ + s) * DEPTH + d);
                        *(float2*)dst = v;
                        float h0, h1;
                        uint32_t hh = pack_hi(v.x, v.y, h0, h1);
                        uint32_t ll = pack_bf2(v.x - h0, v.y - h1);
                        uint32_t* krow = (uint32_t*)((tsr == 1 ? ksp : vsp) + rowi * 128);
                        krow[d >> 1]        = hh;
                        krow[32 + (d >> 1)] = ll;
                    }
                }
            }
        }
    }
}

// ---------------------------------------------------------------------------
// Tensor-core flash attention (split-bf16, exact to ~1.5e-5).
// CTA: 256 threads (8 warps), Br=128 (16 q-rows/warp), Bc=64.
// S accum reused as P A-fragment; V via ldmatrix.trans. Log2-domain scores.
// Writes proj input g_Aao directly in split form.
// ---------------------------------------------------------------------------
#define ATTN_SMEM (32768 + 2*32768)   // Q 32KB + 2 x (K 16KB + V 16KB)

__global__ __launch_bounds__(256, 1)
void attn_mma(const __nv_bfloat16* __restrict__ qs, const __nv_bfloat16* __restrict__ ks,
              const __nv_bfloat16* __restrict__ vs, __nv_bfloat16* __restrict__ aao)
{
    extern __shared__ __align__(128) char smem[];
    const uint32_t QS = smem_u32(smem);

    const int tid  = threadIdx.x;
    const int lane = tid & 31, wid = tid >> 5;
    const int qt = (int)gridDim.x - 1 - (int)blockIdx.x;   // long tiles first
    const int h  = blockIdx.y, b = blockIdx.z;
    const int q0 = qt * 128;
    const size_t bh = ((size_t)b * NHEAD + h) * SEQ;

    const __nv_bfloat16* qg = qs + (bh + q0) * 128;
    const __nv_bfloat16* kg = ks + bh * 128;
    const __nv_bfloat16* vg = vs + bh * 128;

    // Load Q (group 0, together with KV tile 0)
#pragma unroll
    for (int i = 0; i < 8; i++) {
        int idx = i * 256 + tid;
        int row = idx >> 4, cc = idx & 15;
        cp_async16(QS + row * 256 + ((cc ^ (row & 7)) << 4), qg + row * 128 + cc * 8);
    }
    auto loadKV = [&](int kt, int buf) {
        const uint32_t KB = QS + 32768 + buf * 32768;
        const uint32_t VB = KB + 16384;
        const __nv_bfloat16* kp = kg + (size_t)kt * 64 * 128;
        const __nv_bfloat16* vp = vg + (size_t)kt * 64 * 128;
#pragma unroll
        for (int i = 0; i < 4; i++) {
            int idx = i * 256 + tid;
            int row = idx >> 4, cc = idx & 15;
            uint32_t so = row * 256 + ((cc ^ (row & 7)) << 4);
            cp_async16(KB + so, kp + row * 128 + cc * 8);
            cp_async16(VB + so, vp + row * 128 + cc * 8);
        }
    };
    const int ntiles = 2 * qt + 2;
    loadKV(0, 0); CP_COMMIT();
    loadKV(1, 1); CP_COMMIT();

    float m2[2] = { -1e30f, -1e30f };
    float l2[2] = { 0.f, 0.f };
    float oacc[8][4];
#pragma unroll
    for (int j = 0; j < 8; j++)
#pragma unroll
        for (int e = 0; e < 4; e++) oacc[j][e] = 0.f;

    const int arow = wid * 16 + (lane & 15);

    for (int kt = 0; kt < ntiles; kt++) {
        if (kt + 1 < ntiles) { CP_WAIT(1); } else { CP_WAIT(0); }
        __syncthreads();
        const uint32_t KB = QS + 32768 + (kt & 1) * 32768;
        const uint32_t VB = KB + 16384;

        // ---- S = Q''·K''^T (3-term split, log2 domain) ----
        float sacc[8][4];
#pragma unroll
        for (int j = 0; j < 8; j++)
#pragma unroll
            for (int e = 0; e < 4; e++) sacc[j][e] = 0.f;

#pragma unroll
        for (int s = 0; s < 4; s++) {
            uint32_t ah[4], al[4];
            const int ca = s * 2 + (lane >> 4);
            ldmx4(QS + arow * 256 + (((ca     ) ^ (arow & 7)) << 4), ah[0], ah[1], ah[2], ah[3]);
            ldmx4(QS + arow * 256 + (((ca +  8) ^ (arow & 7)) << 4), al[0], al[1], al[2], al[3]);
            uint32_t bh_[8][2], bl_[8][2];
            const int rb = (lane & 7) + ((lane >> 4) << 3);
            const int cb = s * 2 + ((lane >> 3) & 1);
#pragma unroll
            for (int g = 0; g < 4; g++) {
                const int r = g * 16 + rb;
                uint32_t r0, r1, r2, r3;
                ldmx4(KB + r * 256 + (((cb    ) ^ (r & 7)) << 4), r0, r1, r2, r3);
                bh_[2*g][0] = r0; bh_[2*g][1] = r1; bh_[2*g+1][0] = r2; bh_[2*g+1][1] = r3;
                ldmx4(KB + r * 256 + (((cb + 8) ^ (r & 7)) << 4), r0, r1, r2, r3);
                bl_[2*g][0] = r0; bl_[2*g][1] = r1; bl_[2*g+1][0] = r2; bl_[2*g+1][1] = r3;
            }
#pragma unroll
            for (int j = 0; j < 8; j++) {
                mma_bf16(sacc[j], ah[0], ah[1], ah[2], ah[3], bh_[j][0], bh_[j][1]);
                mma_bf16(sacc[j], ah[0], ah[1], ah[2], ah[3], bl_[j][0], bl_[j][1]);
                mma_bf16(sacc[j], al[0], al[1], al[2], al[3], bh_[j][0], bh_[j][1]);
            }
        }

        // ---- causal mask (only last two tiles can cross the diagonal) ----
        if (kt >= 2 * qt) {
            const int k0 = kt * 64;
            const int qr = q0 + wid * 16 + (lane >> 2);
#pragma unroll
            for (int j = 0; j < 8; j++) {
                const int kc = k0 + j * 8 + (lane & 3) * 2;
                if (kc     > qr)     sacc[j][0] = -1e30f;
                if (kc + 1 > qr)     sacc[j][1] = -1e30f;
                if (kc     > qr + 8) sacc[j][2] = -1e30f;
                if (kc + 1 > qr + 8) sacc[j][3] = -1e30f;
            }
        }

        // ---- online softmax (2 rows/thread), build split-P fragments ----
        uint32_t phi[8][2], plo[8][2];
#pragma unroll
        for (int hf = 0; hf < 2; hf++) {
            float mx = -1e30f;
#pragma unroll
            for (int j = 0; j < 8; j++)
                mx = fmaxf(mx, fmaxf(sacc[j][hf*2], sacc[j][hf*2+1]));
            mx = fmaxf(mx, __shfl_xor_sync(0xffffffffu, mx, 1));
            mx = fmaxf(mx, __shfl_xor_sync(0xffffffffu, mx, 2));
            const float newm  = fmaxf(m2[hf], mx);
            const float alpha = exp2_poly(m2[hf] - newm);
            float sum = 0.f;
#pragma unroll
            for (int j = 0; j < 8; j++) {
                float p0 = exp2_poly(sacc[j][hf*2]   - newm);
                float p1 = exp2_poly(sacc[j][hf*2+1] - newm);
                sum += p0 + p1;
                float h0, h1;
                phi[j][hf] = pack_hi(p0, p1, h0, h1);
                plo[j][hf] = pack_bf2(p0 - h0, p1 - h1);
            }
            sum += __shfl_xor_sync(0xffffffffu, sum, 1);
            sum += __shfl_xor_sync(0xffffffffu, sum, 2);
            l2[hf] = l2[hf] * alpha + sum;
            m2[hf] = newm;
#pragma unroll
            for (int j = 0; j < 8; j++) {
                oacc[j][hf*2]   *= alpha;
                oacc[j][hf*2+1] *= alpha;
            }
        }

        // ---- O += P''·V'' (3-term split) ----
#pragma unroll
        for (int s = 0; s < 4; s++) {
            uint32_t pah[4] = { phi[2*s][0], phi[2*s][1], phi[2*s+1][0], phi[2*s+1][1] };
            uint32_t pal[4] = { plo[2*s][0], plo[2*s][1], plo[2*s+1][0], plo[2*s+1][1] };
            const int rv = s * 16 + (lane & 15);
            uint32_t bvh[8][2], bvl[8][2];
#pragma unroll
            for (int np = 0; np < 4; np++) {
                const int cv = np * 2 + (lane >> 4);
                uint32_t r0, r1, r2, r3;
                ldmx4t(VB + rv * 256 + (((cv    ) ^ (rv & 7)) << 4), r0, r1, r2, r3);
                bvh[2*np][0] = r0; bvh[2*np][1] = r1; bvh[2*np+1][0] = r2; bvh[2*np+1][1] = r3;
                ldmx4t(VB + rv * 256 + (((cv + 8) ^ (rv & 7)) << 4), r0, r1, r2, r3);
                bvl[2*np][0] = r0; bvl[2*np][1] = r1; bvl[2*np+1][0] = r2; bvl[2*np+1][1] = r3;
            }
#pragma unroll
            for (int j = 0; j < 8; j++) {
                mma_bf16(oacc[j], pah[0], pah[1], pah[2], pah[3], bvh[j][0], bvh[j][1]);
                mma_bf16(oacc[j], pah[0], pah[1], pah[2], pah[3], bvl[j][0], bvl[j][1]);
                mma_bf16(oacc[j], pal[0], pal[1], pal[2], pal[3], bvh[j][0], bvh[j][1]);
            }
        }

        __syncthreads();
        if (kt + 2 < ntiles) loadKV(kt + 2, kt & 1);
        CP_COMMIT();
    }

    // ---- epilogue: write split proj-input g_Aao [m, 3072] (hi, hi, lo) ----
    const float inv0 = 1.f / l2[0], inv1 = 1.f / l2[1];
    const int r = lane >> 2, cp2 = (lane & 3) * 2;
#pragma unroll
    for (int j = 0; j < 8; j++) {
        const int col = h * 64 + j * 8 + cp2;
#pragma unroll
        for (int hf = 0; hf < 2; hf++) {
            const float inv = hf ? inv1 : inv0;
            const int m = b * SEQ + q0 + wid * 16 + r + hf * 8;
            const float v0 = oacc[j][hf*2]   * inv;
            const float v1 = oacc[j][hf*2+1] * inv;
            float h0, h1;
            uint32_t hh = pack_hi(v0, v1, h0, h1);
            uint32_t ll = pack_bf2(v0 - h0, v1 - h1);
            uint32_t* row = (uint32_t*)(aao + (size_t)m * GK);
            row[col >> 1]            = hh;
            row[(1024 + col) >> 1]   = hh;
            row[(2048 + col) >> 1]   = ll;
        }
    }
}

// ---------------------------------------------------------------------------
extern "C" void kernel_launch(void* const* d_in, const int* in_sizes, int n_in,
                              void* d_out, int out_size)
{
    const float* x      = (const float*)d_in[0];
    const float* w_attn = (const float*)d_in[2];
    const float* b_attn = (const float*)d_in[3];
    const float* w_proj = (const float*)d_in[4];
    const float* b_proj = (const float*)d_in[5];

    float* out     = (float*)d_out;
    float* present = out + (size_t)M_TOTAL * D_MODEL;

    __nv_bfloat16 *gAx, *gAao, *gBq, *gBp, *gqs, *gks, *gvs;
    cudaGetSymbolAddress((void**)&gAx,  g_Ax);
    cudaGetSymbolAddress((void**)&gAao, g_Aao);
    cudaGetSymbolAddress((void**)&gBq,  g_Bqkv);
    cudaGetSymbolAddress((void**)&gBp,  g_Bprj);
    cudaGetSymbolAddress((void**)&gqs,  g_qs);
    cudaGetSymbolAddress((void**)&gks,  g_ks);
    cudaGetSymbolAddress((void**)&gvs,  g_vs);

    static bool attr_set = false;
    if (!attr_set) {
        cudaFuncSetAttribute(attn_mma,    cudaFuncAttributeMaxDynamicSharedMemorySize, ATTN_SMEM);
        cudaFuncSetAttribute(gemm_mma<1>, cudaFuncAttributeMaxDynamicSharedMemorySize, SMEM_MMA);
        cudaFuncSetAttribute(gemm_mma<0>, cudaFuncAttributeMaxDynamicSharedMemorySize, SMEM_MMA);
        attr_set = true;
    }

    // Prep: split-bf16 operands
    conv_a_kernel<<<(M_TOTAL * 256 + 255) / 256, 256>>>(x, gAx);
    conv_w_kernel<<<dim3(3 * D_MODEL / 32, D_MODEL / 32), dim3(32, 8)>>>(w_attn, gBq, 3 * D_MODEL);
    conv_w_kernel<<<dim3(D_MODEL / 32, D_MODEL / 32), dim3(32, 8)>>>(w_proj, gBp, D_MODEL);

    // QKV GEMM with fused split/scale scatter epilogue
    gemm_mma<1><<<dim3(3 * D_MODEL / 128, M_TOTAL / 128), 256, SMEM_MMA>>>(
        gAx, gBq, b_attn, nullptr, present, 3 * D_MODEL, gqs, gks, gvs);

    // Tensor-core flash attention -> writes split proj input directly
    attn_mma<<<dim3(SEQ / 128, NHEAD, BATCH), 256, ATTN_SMEM>>>(gqs, gks, gvs, gAao);

    // Proj GEMM
    gemm_mma<0><<<dim3(D_MODEL / 128, M_TOTAL / 128), 256, SMEM_MMA>>>(
        gAao, gBp, b_proj, out, nullptr, D_MODEL, nullptr, nullptr, nullptr);
}

// round 5
// speedup vs baseline: 2.4647x; 1.0990x over previous
#include <cuda_runtime.h>
#include <cuda_bf16.h>
#include <math_constants.h>
#include <cstdint>

// Problem constants
#define D_MODEL 1024
#define NHEAD   16
#define DEPTH   64
#define BATCH   2
#define SEQ     2048
#define M_TOTAL (BATCH*SEQ)   // 4096
#define GK      3072          // split-bf16 K'' = 3*1024
#define QSCALE  (0.125f * 1.4426950408889634f)   // 1/sqrt(64) * log2(e)

// ---------------------------------------------------------------------------
// Scratch (device globals — no allocation allowed)
// ---------------------------------------------------------------------------
__device__ __nv_bfloat16 g_qs [(size_t)BATCH*NHEAD*SEQ*128];  // q split [b,h,s,(hi64|lo64)], pre-scaled
__device__ __nv_bfloat16 g_ks [(size_t)BATCH*NHEAD*SEQ*128];  // k split
__device__ __nv_bfloat16 g_vs [(size_t)BATCH*NHEAD*SEQ*128];  // v split
__device__ __nv_bfloat16 g_Ax [(size_t)M_TOTAL*GK];           // x split  [M, 3072]
__device__ __nv_bfloat16 g_Aao[(size_t)M_TOTAL*GK];           // attn-out split [M, 3072]
__device__ __nv_bfloat16 g_Bqkv[(size_t)3*D_MODEL*GK];        // w_attn^T split
__device__ __nv_bfloat16 g_Bprj[(size_t)D_MODEL*GK];          // w_proj^T split

// ---------------------------------------------------------------------------
// Helpers
// ---------------------------------------------------------------------------
__device__ __forceinline__ uint32_t smem_u32(const void* p) {
    uint32_t a;
    asm("{ .reg .u64 t; cvta.to.shared.u64 t, %1; cvt.u32.u64 %0, t; }" : "=r"(a) : "l"(p));
    return a;
}
__device__ __forceinline__ void cp_async16(uint32_t saddr, const void* gptr) {
    asm volatile("cp.async.cg.shared.global [%0], [%1], 16;" :: "r"(saddr), "l"(gptr));
}
#define CP_COMMIT() asm volatile("cp.async.commit_group;" ::: "memory")
#define CP_WAIT(n)  asm volatile("cp.async.wait_group %0;" :: "n"(n) : "memory")

__device__ __forceinline__ void ldmx4(uint32_t addr, uint32_t& r0, uint32_t& r1,
                                      uint32_t& r2, uint32_t& r3) {
    asm volatile("ldmatrix.sync.aligned.m8n8.x4.shared.b16 {%0,%1,%2,%3}, [%4];"
                 : "=r"(r0), "=r"(r1), "=r"(r2), "=r"(r3) : "r"(addr));
}
__device__ __forceinline__ void ldmx4t(uint32_t addr, uint32_t& r0, uint32_t& r1,
                                       uint32_t& r2, uint32_t& r3) {
    asm volatile("ldmatrix.sync.aligned.m8n8.x4.trans.shared.b16 {%0,%1,%2,%3}, [%4];"
                 : "=r"(r0), "=r"(r1), "=r"(r2), "=r"(r3) : "r"(addr));
}
__device__ __forceinline__ void mma_bf16(float c[4], uint32_t a0, uint32_t a1,
                                         uint32_t a2, uint32_t a3,
                                         uint32_t b0, uint32_t b1) {
    asm volatile("mma.sync.aligned.m16n8k16.row.col.f32.bf16.bf16.f32 "
                 "{%0,%1,%2,%3}, {%4,%5,%6,%7}, {%8,%9}, {%0,%1,%2,%3};"
                 : "+f"(c[0]), "+f"(c[1]), "+f"(c[2]), "+f"(c[3])
                 : "r"(a0), "r"(a1), "r"(a2), "r"(a3), "r"(b0), "r"(b1));
}

// FMA-pipe exp2 (degree-6; rel err < 3e-6). Inputs expected <= 0.
__device__ __forceinline__ float exp2_poly(float t) {
    t = fmaxf(t, -125.0f);
    float n = floorf(t);
    float f = t - n;
    float p = 1.5403530393381608e-4f;
    p = fmaf(p, f, 1.3333558146428443e-3f);
    p = fmaf(p, f, 9.6181291076284770e-3f);
    p = fmaf(p, f, 5.5504108664821580e-2f);
    p = fmaf(p, f, 2.4022650695910070e-1f);
    p = fmaf(p, f, 6.9314718055994530e-1f);
    p = fmaf(p, f, 1.0f);
    return p * __int_as_float(((int)n + 127) << 23);
}

__device__ __forceinline__ uint32_t pack_hi(float a, float b, float& ha, float& hb) {
    __nv_bfloat162 hh = __floats2bfloat162_rn(a, b);
    ha = __bfloat162float(hh.x);
    hb = __bfloat162float(hh.y);
    return *(uint32_t*)&hh;
}
__device__ __forceinline__ uint32_t pack_bf2(float a, float b) {
    __nv_bfloat162 hh = __floats2bfloat162_rn(a, b);
    return *(uint32_t*)&hh;
}

// ---------------------------------------------------------------------------
// Prep: x[M,1024] fp32 -> A''[M,3072] bf16 segments (hi, hi, lo)
// ---------------------------------------------------------------------------
__global__ __launch_bounds__(256)
void conv_a_kernel(const float* __restrict__ X, __nv_bfloat16* __restrict__ Ad) {
    int i = blockIdx.x * blockDim.x + threadIdx.x;
    if (i >= M_TOTAL * 256) return;
    int m  = i >> 8;
    int kq = (i & 255) << 2;
    float4 v = ((const float4*)X)[i];
    union { __nv_bfloat16 h[4]; uint2 u; } hi, lo;
    hi.h[0] = __float2bfloat16(v.x); lo.h[0] = __float2bfloat16(v.x - __bfloat162float(hi.h[0]));
    hi.h[1] = __float2bfloat16(v.y); lo.h[1] = __float2bfloat16(v.y - __bfloat162float(hi.h[1]));
    hi.h[2] = __float2bfloat16(v.z); lo.h[2] = __float2bfloat16(v.z - __bfloat162float(hi.h[2]));
    hi.h[3] = __float2bfloat16(v.w); lo.h[3] = __float2bfloat16(v.w - __bfloat162float(hi.h[3]));
    size_t base = (size_t)m * GK + kq;
    *(uint2*)(Ad + base)        = hi.u;
    *(uint2*)(Ad + base + 1024) = hi.u;
    *(uint2*)(Ad + base + 2048) = lo.u;
}

// ---------------------------------------------------------------------------
// Prep: w[1024,N] fp32 -> B''[N,3072] bf16 (transposed; segments hi, lo, hi)
// ---------------------------------------------------------------------------
__global__ __launch_bounds__(256)
void conv_w_kernel(const float* __restrict__ W, __nv_bfloat16* __restrict__ Bd, int N) {
    __shared__ float t[32][33];
    const int k0 = blockIdx.y * 32, n0 = blockIdx.x * 32;
    for (int r = threadIdx.y; r < 32; r += 8)
        t[r][threadIdx.x] = W[(size_t)(k0 + r) * N + n0 + threadIdx.x];
    __syncthreads();
    for (int r = threadIdx.y; r < 32; r += 8) {
        const int n = n0 + r, k = k0 + threadIdx.x;
        float v = t[threadIdx.x][r];
        __nv_bfloat16 h  = __float2bfloat16(v);
        __nv_bfloat16 lo = __float2bfloat16(v - __bfloat162float(h));
        __nv_bfloat16* row = Bd + (size_t)n * GK;
        row[k]        = h;
        row[1024 + k] = lo;
        row[2048 + k] = h;
    }
}

// ---------------------------------------------------------------------------
// mma.sync bf16 GEMM: D[M,N] = A''[M,GK] @ B''[N,GK]^T + bias
// 128x128 tile, BK=64, 3-stage cp.async, forced 2 CTAs/SM (regs<=128).
// QKV=1: q -> g_qs (scaled, split bf16), k/v -> present fp32 + g_ks/g_vs bf16.
// QKV=0: row-major fp32 out0.
// ---------------------------------------------------------------------------
#define NKIT (GK/64)          // 48
#define STG_BYTES 32768
#define SMEM_MMA (3*STG_BYTES)

template<int QKV>
__global__ __launch_bounds__(256, 2)
void gemm_mma(const __nv_bfloat16* __restrict__ A, const __nv_bfloat16* __restrict__ B,
              const float* __restrict__ bias, float* __restrict__ out0,
              float* __restrict__ present, int N,
              __nv_bfloat16* __restrict__ qsp, __nv_bfloat16* __restrict__ ksp,
              __nv_bfloat16* __restrict__ vsp)
{
    extern __shared__ __align__(128) char smem[];
    const uint32_t sbase = smem_u32(smem);

    const int tid  = threadIdx.x;
    const int lane = tid & 31, wid = tid >> 5;
    const int m0 = blockIdx.y * 128, n0 = blockIdx.x * 128;
    const int wm0 = (wid >> 2) * 64;
    const int wn0 = (wid & 3) * 32;

    const int lrow = tid >> 1;
    const int lc0  = (tid & 1) * 4;
    const __nv_bfloat16* aG = A + (size_t)(m0 + lrow) * GK;
    const __nv_bfloat16* bG = B + (size_t)(n0 + lrow) * GK;
    const uint32_t wOffBase = (uint32_t)lrow * 128;

    float c[4][4][4];
#pragma unroll
    for (int mi = 0; mi < 4; mi++)
#pragma unroll
        for (int ni = 0; ni < 4; ni++)
#pragma unroll
            for (int e = 0; e < 4; e++) c[mi][ni][e] = 0.f;

    auto load_stage = [&](int st, int kt) {
        const uint32_t s0 = sbase + st * STG_BYTES;
        const __nv_bfloat16* ag = aG + kt * 64;
        const __nv_bfloat16* bg = bG + kt * 64;
#pragma unroll
        for (int i = 0; i < 4; i++) {
            uint32_t wo = wOffBase + (uint32_t)(((lc0 + i) ^ (lrow & 7)) << 4);
            cp_async16(s0 + wo,         ag + (lc0 + i) * 8);
            cp_async16(s0 + 16384 + wo, bg + (lc0 + i) * 8);
        }
    };

    auto compute = [&](int st) {
        const uint32_t sA = sbase + st * STG_BYTES;
        const uint32_t sB = sA + 16384;
#pragma unroll
        for (int ks = 0; ks < 4; ks++) {
            uint32_t a[4][4];
#pragma unroll
            for (int mi = 0; mi < 4; mi++) {
                const int r  = wm0 + mi * 16 + (lane & 15);
                const int cc = ks * 2 + (lane >> 4);
                ldmx4(sA + r * 128 + (((cc ^ (r & 7))) << 4),
                      a[mi][0], a[mi][1], a[mi][2], a[mi][3]);
            }
            uint32_t b[4][2];
#pragma unroll
            for (int np = 0; np < 2; np++) {
                const int r  = wn0 + np * 16 + (lane & 7) + ((lane >> 4) << 3);
                const int cc = ks * 2 + ((lane >> 3) & 1);
                uint32_t r0, r1, r2, r3;
                ldmx4(sB + r * 128 + (((cc ^ (r & 7))) << 4), r0, r1, r2, r3);
                b[np * 2][0] = r0; b[np * 2][1] = r1;
                b[np * 2 + 1][0] = r2; b[np * 2 + 1][1] = r3;
            }
#pragma unroll
            for (int mi = 0; mi < 4; mi++)
#pragma unroll
                for (int ni = 0; ni < 4; ni++)
                    mma_bf16(c[mi][ni], a[mi][0], a[mi][1], a[mi][2], a[mi][3],
                             b[ni][0], b[ni][1]);
        }
    };

    load_stage(0, 0); CP_COMMIT();
    load_stage(1, 1); CP_COMMIT();

    for (int kt = 0; kt < NKIT; kt++) {
        CP_WAIT(1);
        __syncthreads();
        if (kt + 2 < NKIT) load_stage((kt + 2) % 3, kt + 2);
        CP_COMMIT();
        compute(kt % 3);
    }

    const int gr = lane >> 2, tc = lane & 3;
#pragma unroll
    for (int mi = 0; mi < 4; mi++) {
#pragma unroll
        for (int rr = 0; rr < 2; rr++) {
            const int m = m0 + wm0 + mi * 16 + gr + rr * 8;
            const int bidx = m >> 11, s = m & (SEQ - 1);
#pragma unroll
            for (int ni = 0; ni < 4; ni++) {
                const int n = n0 + wn0 + ni * 8 + tc * 2;
                float2 bb = *(const float2*)(bias + n);
                float2 v;
                v.x = c[mi][ni][rr * 2 + 0] + bb.x;
                v.y = c[mi][ni][rr * 2 + 1] + bb.y;
                if (QKV == 0) {
                    *(float2*)&out0[(size_t)m * N + n] = v;
                } else {
                    const int tsr = n >> 10;           // 0=q 1=k 2=v
                    const int nn  = n & (D_MODEL - 1);
                    const int h   = nn >> 6, d = nn & 63;
                    const size_t rowi = ((size_t)bidx * NHEAD + h) * SEQ + s;
                    if (tsr == 0) {
                        float q0v = v.x * QSCALE, q1v = v.y * QSCALE;
                        float h0, h1;
                        uint32_t hh = pack_hi(q0v, q1v, h0, h1);
                        uint32_t ll = pack_bf2(q0v - h0, q1v - h1);
                        uint32_t* qrow = (uint32_t*)(qsp + rowi * 128);
                        qrow[d >> 1]        = hh;
                        qrow[32 + (d >> 1)] = ll;
                    } else {
                        float* dst = present +
                            ((((size_t)(bidx * 2 + (tsr - 1)) * NHEAD + h) * SEQ + s) * DEPTH + d);
                        *(float2*)dst = v;
                        float h0, h1;
                        uint32_t hh = pack_hi(v.x, v.y, h0, h1);
                        uint32_t ll = pack_bf2(v.x - h0, v.y - h1);
                        uint32_t* krow = (uint32_t*)((tsr == 1 ? ksp : vsp) + rowi * 128);
                        krow[d >> 1]        = hh;
                        krow[32 + (d >> 1)] = ll;
                    }
                }
            }
        }
    }
}

// ---------------------------------------------------------------------------
// Tensor-core flash attention (split-bf16, exact to ~1.5e-5).
// CTA: 256 threads (8 warps), Br=128 (16 q-rows/warp), Bc=64.
// ---------------------------------------------------------------------------
#define ATTN_SMEM (32768 + 2*32768)   // Q 32KB + 2 x (K 16KB + V 16KB)

__global__ __launch_bounds__(256, 1)
void attn_mma(const __nv_bfloat16* __restrict__ qs, const __nv_bfloat16* __restrict__ ks,
              const __nv_bfloat16* __restrict__ vs, __nv_bfloat16* __restrict__ aao)
{
    extern __shared__ __align__(128) char smem[];
    const uint32_t QS = smem_u32(smem);

    const int tid  = threadIdx.x;
    const int lane = tid & 31, wid = tid >> 5;
    const int qt = (int)gridDim.x - 1 - (int)blockIdx.x;   // long tiles first
    const int h  = blockIdx.y, b = blockIdx.z;
    const int q0 = qt * 128;
    const size_t bh = ((size_t)b * NHEAD + h) * SEQ;

    const __nv_bfloat16* qg = qs + (bh + q0) * 128;
    const __nv_bfloat16* kg = ks + bh * 128;
    const __nv_bfloat16* vg = vs + bh * 128;

#pragma unroll
    for (int i = 0; i < 8; i++) {
        int idx = i * 256 + tid;
        int row = idx >> 4, cc = idx & 15;
        cp_async16(QS + row * 256 + ((cc ^ (row & 7)) << 4), qg + row * 128 + cc * 8);
    }
    auto loadKV = [&](int kt, int buf) {
        const uint32_t KB = QS + 32768 + buf * 32768;
        const uint32_t VB = KB + 16384;
        const __nv_bfloat16* kp = kg + (size_t)kt * 64 * 128;
        const __nv_bfloat16* vp = vg + (size_t)kt * 64 * 128;
#pragma unroll
        for (int i = 0; i < 4; i++) {
            int idx = i * 256 + tid;
            int row = idx >> 4, cc = idx & 15;
            uint32_t so = row * 256 + ((cc ^ (row & 7)) << 4);
            cp_async16(KB + so, kp + row * 128 + cc * 8);
            cp_async16(VB + so, vp + row * 128 + cc * 8);
        }
    };
    const int ntiles = 2 * qt + 2;
    loadKV(0, 0); CP_COMMIT();
    loadKV(1, 1); CP_COMMIT();

    float m2[2] = { -1e30f, -1e30f };
    float l2[2] = { 0.f, 0.f };
    float oacc[8][4];
#pragma unroll
    for (int j = 0; j < 8; j++)
#pragma unroll
        for (int e = 0; e < 4; e++) oacc[j][e] = 0.f;

    const int arow = wid * 16 + (lane & 15);

    for (int kt = 0; kt < ntiles; kt++) {
        if (kt + 1 < ntiles) { CP_WAIT(1); } else { CP_WAIT(0); }
        __syncthreads();
        const uint32_t KB = QS + 32768 + (kt & 1) * 32768;
        const uint32_t VB = KB + 16384;

        float sacc[8][4];
#pragma unroll
        for (int j = 0; j < 8; j++)
#pragma unroll
            for (int e = 0; e < 4; e++) sacc[j][e] = 0.f;

#pragma unroll
        for (int s = 0; s < 4; s++) {
            uint32_t ah[4], al[4];
            const int ca = s * 2 + (lane >> 4);
            ldmx4(QS + arow * 256 + (((ca     ) ^ (arow & 7)) << 4), ah[0], ah[1], ah[2], ah[3]);
            ldmx4(QS + arow * 256 + (((ca +  8) ^ (arow & 7)) << 4), al[0], al[1], al[2], al[3]);
            uint32_t bh_[8][2], bl_[8][2];
            const int rb = (lane & 7) + ((lane >> 4) << 3);
            const int cb = s * 2 + ((lane >> 3) & 1);
#pragma unroll
            for (int g = 0; g < 4; g++) {
                const int r = g * 16 + rb;
                uint32_t r0, r1, r2, r3;
                ldmx4(KB + r * 256 + (((cb    ) ^ (r & 7)) << 4), r0, r1, r2, r3);
                bh_[2*g][0] = r0; bh_[2*g][1] = r1; bh_[2*g+1][0] = r2; bh_[2*g+1][1] = r3;
                ldmx4(KB + r * 256 + (((cb + 8) ^ (r & 7)) << 4), r0, r1, r2, r3);
                bl_[2*g][0] = r0; bl_[2*g][1] = r1; bl_[2*g+1][0] = r2; bl_[2*g+1][1] = r3;
            }
#pragma unroll
            for (int j = 0; j < 8; j++) {
                mma_bf16(sacc[j], ah[0], ah[1], ah[2], ah[3], bh_[j][0], bh_[j][1]);
                mma_bf16(sacc[j], ah[0], ah[1], ah[2], ah[3], bl_[j][0], bl_[j][1]);
                mma_bf16(sacc[j], al[0], al[1], al[2], al[3], bh_[j][0], bh_[j][1]);
            }
        }

        if (kt >= 2 * qt) {
            const int k0 = kt * 64;
            const int qr = q0 + wid * 16 + (lane >> 2);
#pragma unroll
            for (int j = 0; j < 8; j++) {
                const int kc = k0 + j * 8 + (lane & 3) * 2;
                if (kc     > qr)     sacc[j][0] = -1e30f;
                if (kc + 1 > qr)     sacc[j][1] = -1e30f;
                if (kc     > qr + 8) sacc[j][2] = -1e30f;
                if (kc + 1 > qr + 8) sacc[j][3] = -1e30f;
            }
        }

        uint32_t phi[8][2], plo[8][2];
#pragma unroll
        for (int hf = 0; hf < 2; hf++) {
            float mx = -1e30f;
#pragma unroll
            for (int j = 0; j < 8; j++)
                mx = fmaxf(mx, fmaxf(sacc[j][hf*2], sacc[j][hf*2+1]));
            mx = fmaxf(mx, __shfl_xor_sync(0xffffffffu, mx, 1));
            mx = fmaxf(mx, __shfl_xor_sync(0xffffffffu, mx, 2));
            const float newm  = fmaxf(m2[hf], mx);
            const float alpha = exp2_poly(m2[hf] - newm);
            float sum = 0.f;
#pragma unroll
            for (int j = 0; j < 8; j++) {
                float p0 = exp2_poly(sacc[j][hf*2]   - newm);
                float p1 = exp2_poly(sacc[j][hf*2+1] - newm);
                sum += p0 + p1;
                float h0, h1;
                phi[j][hf] = pack_hi(p0, p1, h0, h1);
                plo[j][hf] = pack_bf2(p0 - h0, p1 - h1);
            }
            sum += __shfl_xor_sync(0xffffffffu, sum, 1);
            sum += __shfl_xor_sync(0xffffffffu, sum, 2);
            l2[hf] = l2[hf] * alpha + sum;
            m2[hf] = newm;
#pragma unroll
            for (int j = 0; j < 8; j++) {
                oacc[j][hf*2]   *= alpha;
                oacc[j][hf*2+1] *= alpha;
            }
        }

#pragma unroll
        for (int s = 0; s < 4; s++) {
            uint32_t pah[4] = { phi[2*s][0], phi[2*s][1], phi[2*s+1][0], phi[2*s+1][1] };
            uint32_t pal[4] = { plo[2*s][0], plo[2*s][1], plo[2*s+1][0], plo[2*s+1][1] };
            const int rv = s * 16 + (lane & 15);
            uint32_t bvh[8][2], bvl[8][2];
#pragma unroll
            for (int np = 0; np < 4; np++) {
                const int cv = np * 2 + (lane >> 4);
                uint32_t r0, r1, r2, r3;
                ldmx4t(VB + rv * 256 + (((cv    ) ^ (rv & 7)) << 4), r0, r1, r2, r3);
                bvh[2*np][0] = r0; bvh[2*np][1] = r1; bvh[2*np+1][0] = r2; bvh[2*np+1][1] = r3;
                ldmx4t(VB + rv * 256 + (((cv + 8) ^ (rv & 7)) << 4), r0, r1, r2, r3);
                bvl[2*np][0] = r0; bvl[2*np][1] = r1; bvl[2*np+1][0] = r2; bvl[2*np+1][1] = r3;
            }
#pragma unroll
            for (int j = 0; j < 8; j++) {
                mma_bf16(oacc[j], pah[0], pah[1], pah[2], pah[3], bvh[j][0], bvh[j][1]);
                mma_bf16(oacc[j], pah[0], pah[1], pah[2], pah[3], bvl[j][0], bvl[j][1]);
                mma_bf16(oacc[j], pal[0], pal[1], pal[2], pal[3], bvh[j][0], bvh[j][1]);
            }
        }

        __syncthreads();
        if (kt + 2 < ntiles) loadKV(kt + 2, kt & 1);
        CP_COMMIT();
    }

    const float inv0 = 1.f / l2[0], inv1 = 1.f / l2[1];
    const int r = lane >> 2, cp2 = (lane & 3) * 2;
#pragma unroll
    for (int j = 0; j < 8; j++) {
        const int col = h * 64 + j * 8 + cp2;
#pragma unroll
        for (int hf = 0; hf < 2; hf++) {
            const float inv = hf ? inv1 : inv0;
            const int m = b * SEQ + q0 + wid * 16 + r + hf * 8;
            const float v0 = oacc[j][hf*2]   * inv;
            const float v1 = oacc[j][hf*2+1] * inv;
            float h0, h1;
            uint32_t hh = pack_hi(v0, v1, h0, h1);
            uint32_t ll = pack_bf2(v0 - h0, v1 - h1);
            uint32_t* row = (uint32_t*)(aao + (size_t)m * GK);
            row[col >> 1]            = hh;
            row[(1024 + col) >> 1]   = hh;
            row[(2048 + col) >> 1]   = ll;
        }
    }
}

// ---------------------------------------------------------------------------
extern "C" void kernel_launch(void* const* d_in, const int* in_sizes, int n_in,
                              void* d_out, int out_size)
{
    const float* x      = (const float*)d_in[0];
    const float* w_attn = (const float*)d_in[2];
    const float* b_attn = (const float*)d_in[3];
    const float* w_proj = (const float*)d_in[4];
    const float* b_proj = (const float*)d_in[5];

    float* out     = (float*)d_out;
    float* present = out + (size_t)M_TOTAL * D_MODEL;

    __nv_bfloat16 *gAx, *gAao, *gBq, *gBp, *gqs, *gks, *gvs;
    cudaGetSymbolAddress((void**)&gAx,  g_Ax);
    cudaGetSymbolAddress((void**)&gAao, g_Aao);
    cudaGetSymbolAddress((void**)&gBq,  g_Bqkv);
    cudaGetSymbolAddress((void**)&gBp,  g_Bprj);
    cudaGetSymbolAddress((void**)&gqs,  g_qs);
    cudaGetSymbolAddress((void**)&gks,  g_ks);
    cudaGetSymbolAddress((void**)&gvs,  g_vs);

    static bool attr_set = false;
    if (!attr_set) {
        cudaFuncSetAttribute(attn_mma,    cudaFuncAttributeMaxDynamicSharedMemorySize, ATTN_SMEM);
        cudaFuncSetAttribute(gemm_mma<1>, cudaFuncAttributeMaxDynamicSharedMemorySize, SMEM_MMA);
        cudaFuncSetAttribute(gemm_mma<0>, cudaFuncAttributeMaxDynamicSharedMemorySize, SMEM_MMA);
        attr_set = true;
    }

    // Prep: split-bf16 operands
    conv_a_kernel<<<(M_TOTAL * 256 + 255) / 256, 256>>>(x, gAx);
    conv_w_kernel<<<dim3(3 * D_MODEL / 32, D_MODEL / 32), dim3(32, 8)>>>(w_attn, gBq, 3 * D_MODEL);
    conv_w_kernel<<<dim3(D_MODEL / 32, D_MODEL / 32), dim3(32, 8)>>>(w_proj, gBp, D_MODEL);

    // QKV GEMM with fused split/scale scatter epilogue
    gemm_mma<1><<<dim3(3 * D_MODEL / 128, M_TOTAL / 128), 256, SMEM_MMA>>>(
        gAx, gBq, b_attn, nullptr, present, 3 * D_MODEL, gqs, gks, gvs);

    // Tensor-core flash attention -> writes split proj input directly
    attn_mma<<<dim3(SEQ / 128, NHEAD, BATCH), 256, ATTN_SMEM>>>(gqs, gks, gvs, gAao);

    // Proj GEMM
    gemm_mma<0><<<dim3(D_MODEL / 128, M_TOTAL / 128), 256, SMEM_MMA>>>(
        gAao, gBp, b_proj, out, nullptr, D_MODEL, nullptr, nullptr, nullptr);
}

// round 6
// speedup vs baseline: 2.4797x; 1.0061x over previous
#include <cuda_runtime.h>
#include <cuda_bf16.h>
#include <math_constants.h>
#include <cstdint>

// Problem constants
#define D_MODEL 1024
#define NHEAD   16
#define DEPTH   64
#define BATCH   2
#define SEQ     2048
#define M_TOTAL (BATCH*SEQ)   // 4096
#define GK      3072          // split-bf16 K'' = 3*1024
#define QSCALE  (0.125f * 1.4426950408889634f)   // 1/sqrt(64) * log2(e)

// ---------------------------------------------------------------------------
// Scratch (device globals — no allocation allowed)
// ---------------------------------------------------------------------------
__device__ __nv_bfloat16 g_qs [(size_t)BATCH*NHEAD*SEQ*128];  // q split, pre-scaled
__device__ __nv_bfloat16 g_ks [(size_t)BATCH*NHEAD*SEQ*128];  // k split
__device__ __nv_bfloat16 g_vs [(size_t)BATCH*NHEAD*SEQ*128];  // v split
__device__ __nv_bfloat16 g_Ax [(size_t)M_TOTAL*GK];           // x split  [M, 3072]
__device__ __nv_bfloat16 g_Aao[(size_t)M_TOTAL*GK];           // attn-out split [M, 3072]
__device__ __nv_bfloat16 g_Bqkv[(size_t)3*D_MODEL*GK];        // w_attn^T split
__device__ __nv_bfloat16 g_Bprj[(size_t)D_MODEL*GK];          // w_proj^T split

// ---------------------------------------------------------------------------
// Helpers
// ---------------------------------------------------------------------------
__device__ __forceinline__ uint32_t smem_u32(const void* p) {
    uint32_t a;
    asm("{ .reg .u64 t; cvta.to.shared.u64 t, %1; cvt.u32.u64 %0, t; }" : "=r"(a) : "l"(p));
    return a;
}
__device__ __forceinline__ void cp_async16(uint32_t saddr, const void* gptr) {
    asm volatile("cp.async.cg.shared.global [%0], [%1], 16;" :: "r"(saddr), "l"(gptr));
}
#define CP_COMMIT() asm volatile("cp.async.commit_group;" ::: "memory")
#define CP_WAIT(n)  asm volatile("cp.async.wait_group %0;" :: "n"(n) : "memory")

__device__ __forceinline__ void ldmx4(uint32_t addr, uint32_t& r0, uint32_t& r1,
                                      uint32_t& r2, uint32_t& r3) {
    asm volatile("ldmatrix.sync.aligned.m8n8.x4.shared.b16 {%0,%1,%2,%3}, [%4];"
                 : "=r"(r0), "=r"(r1), "=r"(r2), "=r"(r3) : "r"(addr));
}
__device__ __forceinline__ void ldmx4t(uint32_t addr, uint32_t& r0, uint32_t& r1,
                                       uint32_t& r2, uint32_t& r3) {
    asm volatile("ldmatrix.sync.aligned.m8n8.x4.trans.shared.b16 {%0,%1,%2,%3}, [%4];"
                 : "=r"(r0), "=r"(r1), "=r"(r2), "=r"(r3) : "r"(addr));
}
__device__ __forceinline__ void mma_bf16(float c[4], uint32_t a0, uint32_t a1,
                                         uint32_t a2, uint32_t a3,
                                         uint32_t b0, uint32_t b1) {
    asm volatile("mma.sync.aligned.m16n8k16.row.col.f32.bf16.bf16.f32 "
                 "{%0,%1,%2,%3}, {%4,%5,%6,%7}, {%8,%9}, {%0,%1,%2,%3};"
                 : "+f"(c[0]), "+f"(c[1]), "+f"(c[2]), "+f"(c[3])
                 : "r"(a0), "r"(a1), "r"(a2), "r"(a3), "r"(b0), "r"(b1));
}

// FMA-pipe exp2 (degree-6; rel err < 3e-6). Inputs expected <= 0.
__device__ __forceinline__ float exp2_poly(float t) {
    t = fmaxf(t, -125.0f);
    float n = floorf(t);
    float f = t - n;
    float p = 1.5403530393381608e-4f;
    p = fmaf(p, f, 1.3333558146428443e-3f);
    p = fmaf(p, f, 9.6181291076284770e-3f);
    p = fmaf(p, f, 5.5504108664821580e-2f);
    p = fmaf(p, f, 2.4022650695910070e-1f);
    p = fmaf(p, f, 6.9314718055994530e-1f);
    p = fmaf(p, f, 1.0f);
    return p * __int_as_float(((int)n + 127) << 23);
}

__device__ __forceinline__ uint32_t pack_hi(float a, float b, float& ha, float& hb) {
    __nv_bfloat162 hh = __floats2bfloat162_rn(a, b);
    ha = __bfloat162float(hh.x);
    hb = __bfloat162float(hh.y);
    return *(uint32_t*)&hh;
}
__device__ __forceinline__ uint32_t pack_bf2(float a, float b) {
    __nv_bfloat162 hh = __floats2bfloat162_rn(a, b);
    return *(uint32_t*)&hh;
}

// ---------------------------------------------------------------------------
// Prep: x[M,1024] fp32 -> A''[M,3072] bf16 segments (hi, hi, lo)
// ---------------------------------------------------------------------------
__global__ __launch_bounds__(256)
void conv_a_kernel(const float* __restrict__ X, __nv_bfloat16* __restrict__ Ad) {
    int i = blockIdx.x * blockDim.x + threadIdx.x;
    if (i >= M_TOTAL * 256) return;
    int m  = i >> 8;
    int kq = (i & 255) << 2;
    float4 v = ((const float4*)X)[i];
    union { __nv_bfloat16 h[4]; uint2 u; } hi, lo;
    hi.h[0] = __float2bfloat16(v.x); lo.h[0] = __float2bfloat16(v.x - __bfloat162float(hi.h[0]));
    hi.h[1] = __float2bfloat16(v.y); lo.h[1] = __float2bfloat16(v.y - __bfloat162float(hi.h[1]));
    hi.h[2] = __float2bfloat16(v.z); lo.h[2] = __float2bfloat16(v.z - __bfloat162float(hi.h[2]));
    hi.h[3] = __float2bfloat16(v.w); lo.h[3] = __float2bfloat16(v.w - __bfloat162float(hi.h[3]));
    size_t base = (size_t)m * GK + kq;
    *(uint2*)(Ad + base)        = hi.u;
    *(uint2*)(Ad + base + 1024) = hi.u;
    *(uint2*)(Ad + base + 2048) = lo.u;
}

// ---------------------------------------------------------------------------
// Prep: w[1024,N] fp32 -> B''[N,3072] bf16 (transposed; segments hi, lo, hi)
// ---------------------------------------------------------------------------
__global__ __launch_bounds__(256)
void conv_w_kernel(const float* __restrict__ W, __nv_bfloat16* __restrict__ Bd, int N) {
    __shared__ float t[32][33];
    const int k0 = blockIdx.y * 32, n0 = blockIdx.x * 32;
    for (int r = threadIdx.y; r < 32; r += 8)
        t[r][threadIdx.x] = W[(size_t)(k0 + r) * N + n0 + threadIdx.x];
    __syncthreads();
    for (int r = threadIdx.y; r < 32; r += 8) {
        const int n = n0 + r, k = k0 + threadIdx.x;
        float v = t[threadIdx.x][r];
        __nv_bfloat16 h  = __float2bfloat16(v);
        __nv_bfloat16 lo = __float2bfloat16(v - __bfloat162float(h));
        __nv_bfloat16* row = Bd + (size_t)n * GK;
        row[k]        = h;
        row[1024 + k] = lo;
        row[2048 + k] = h;
    }
}

// ---------------------------------------------------------------------------
// mma.sync bf16 GEMM with register double-buffered fragments.
// 128x128 tile, BK=64, 3-stage cp.async, 2 CTAs/SM.
// ---------------------------------------------------------------------------
#define NKIT (GK/64)          // 48
#define STG_BYTES 32768
#define SMEM_MMA (3*STG_BYTES)

template<int QKV>
__global__ __launch_bounds__(256, 2)
void gemm_mma(const __nv_bfloat16* __restrict__ A, const __nv_bfloat16* __restrict__ B,
              const float* __restrict__ bias, float* __restrict__ out0,
              float* __restrict__ present, int N,
              __nv_bfloat16* __restrict__ qsp, __nv_bfloat16* __restrict__ ksp,
              __nv_bfloat16* __restrict__ vsp)
{
    extern __shared__ __align__(128) char smem[];
    const uint32_t sbase = smem_u32(smem);

    const int tid  = threadIdx.x;
    const int lane = tid & 31, wid = tid >> 5;
    const int m0 = blockIdx.y * 128, n0 = blockIdx.x * 128;
    const int wm0 = (wid >> 2) * 64;
    const int wn0 = (wid & 3) * 32;

    const int lrow = tid >> 1;
    const int lc0  = (tid & 1) * 4;
    const __nv_bfloat16* aG = A + (size_t)(m0 + lrow) * GK;
    const __nv_bfloat16* bG = B + (size_t)(n0 + lrow) * GK;
    const uint32_t wOffBase = (uint32_t)lrow * 128;

    float c[4][4][4];
#pragma unroll
    for (int mi = 0; mi < 4; mi++)
#pragma unroll
        for (int ni = 0; ni < 4; ni++)
#pragma unroll
            for (int e = 0; e < 4; e++) c[mi][ni][e] = 0.f;

    auto load_stage = [&](int st, int kt) {
        const uint32_t s0 = sbase + st * STG_BYTES;
        const __nv_bfloat16* ag = aG + kt * 64;
        const __nv_bfloat16* bg = bG + kt * 64;
#pragma unroll
        for (int i = 0; i < 4; i++) {
            uint32_t wo = wOffBase + (uint32_t)(((lc0 + i) ^ (lrow & 7)) << 4);
            cp_async16(s0 + wo,         ag + (lc0 + i) * 8);
            cp_async16(s0 + 16384 + wo, bg + (lc0 + i) * 8);
        }
    };

    // Fragment loaders (warp-tile addresses precomputed per call)
    auto load_a = [&](uint32_t sA, int ks, uint32_t a[4][4]) {
        const int cc = ks * 2 + (lane >> 4);
#pragma unroll
        for (int mi = 0; mi < 4; mi++) {
            const int r = wm0 + mi * 16 + (lane & 15);
            ldmx4(sA + r * 128 + (((cc ^ (r & 7))) << 4),
                  a[mi][0], a[mi][1], a[mi][2], a[mi][3]);
        }
    };
    auto load_b = [&](uint32_t sB, int ks, uint32_t b[4][2]) {
        const int cc = ks * 2 + ((lane >> 3) & 1);
        const int rbase = wn0 + (lane & 7) + ((lane >> 4) << 3);
#pragma unroll
        for (int np = 0; np < 2; np++) {
            const int r = rbase + np * 16;
            uint32_t r0, r1, r2, r3;
            ldmx4(sB + r * 128 + (((cc ^ (r & 7))) << 4), r0, r1, r2, r3);
            b[np * 2][0] = r0;     b[np * 2][1] = r1;
            b[np * 2 + 1][0] = r2; b[np * 2 + 1][1] = r3;
        }
    };

    auto compute = [&](int st) {
        const uint32_t sA = sbase + st * STG_BYTES;
        const uint32_t sB = sA + 16384;
        uint32_t a[2][4][4], b[2][4][2];
        load_a(sA, 0, a[0]);
        load_b(sB, 0, b[0]);
#pragma unroll
        for (int ks = 0; ks < 4; ks++) {
            const int cur = ks & 1, nxt = cur ^ 1;
            if (ks < 3) {
                load_a(sA, ks + 1, a[nxt]);
                load_b(sB, ks + 1, b[nxt]);
            }
#pragma unroll
            for (int mi = 0; mi < 4; mi++)
#pragma unroll
                for (int ni = 0; ni < 4; ni++)
                    mma_bf16(c[mi][ni], a[cur][mi][0], a[cur][mi][1],
                             a[cur][mi][2], a[cur][mi][3],
                             b[cur][ni][0], b[cur][ni][1]);
        }
    };

    load_stage(0, 0); CP_COMMIT();
    load_stage(1, 1); CP_COMMIT();

    for (int kt = 0; kt < NKIT; kt++) {
        CP_WAIT(1);
        __syncthreads();
        if (kt + 2 < NKIT) load_stage((kt + 2) % 3, kt + 2);
        CP_COMMIT();
        compute(kt % 3);
    }

    const int gr = lane >> 2, tc = lane & 3;
#pragma unroll
    for (int mi = 0; mi < 4; mi++) {
#pragma unroll
        for (int rr = 0; rr < 2; rr++) {
            const int m = m0 + wm0 + mi * 16 + gr + rr * 8;
            const int bidx = m >> 11, s = m & (SEQ - 1);
#pragma unroll
            for (int ni = 0; ni < 4; ni++) {
                const int n = n0 + wn0 + ni * 8 + tc * 2;
                float2 bb = *(const float2*)(bias + n);
                float2 v;
                v.x = c[mi][ni][rr * 2 + 0] + bb.x;
                v.y = c[mi][ni][rr * 2 + 1] + bb.y;
                if (QKV == 0) {
                    *(float2*)&out0[(size_t)m * N + n] = v;
                } else {
                    const int tsr = n >> 10;           // 0=q 1=k 2=v
                    const int nn  = n & (D_MODEL - 1);
                    const int h   = nn >> 6, d = nn & 63;
                    const size_t rowi = ((size_t)bidx * NHEAD + h) * SEQ + s;
                    if (tsr == 0) {
                        float q0v = v.x * QSCALE, q1v = v.y * QSCALE;
                        float h0, h1;
                        uint32_t hh = pack_hi(q0v, q1v, h0, h1);
                        uint32_t ll = pack_bf2(q0v - h0, q1v - h1);
                        uint32_t* qrow = (uint32_t*)(qsp + rowi * 128);
                        qrow[d >> 1]        = hh;
                        qrow[32 + (d >> 1)] = ll;
                    } else {
                        float* dst = present +
                            ((((size_t)(bidx * 2 + (tsr - 1)) * NHEAD + h) * SEQ + s) * DEPTH + d);
                        *(float2*)dst = v;
                        float h0, h1;
                        uint32_t hh = pack_hi(v.x, v.y, h0, h1);
                        uint32_t ll = pack_bf2(v.x - h0, v.y - h1);
                        uint32_t* krow = (uint32_t*)((tsr == 1 ? ksp : vsp) + rowi * 128);
                        krow[d >> 1]        = hh;
                        krow[32 + (d >> 1)] = ll;
                    }
                }
            }
        }
    }
}

// ---------------------------------------------------------------------------
// Tensor-core flash attention (split-bf16, exact to ~1.5e-5).
// CTA: 256 threads (8 warps), Br=128 (16 q-rows/warp), Bc=64.
// ---------------------------------------------------------------------------
#define ATTN_SMEM (32768 + 2*32768)   // Q 32KB + 2 x (K 16KB + V 16KB)

__global__ __launch_bounds__(256, 1)
void attn_mma(const __nv_bfloat16* __restrict__ qs, const __nv_bfloat16* __restrict__ ks,
              const __nv_bfloat16* __restrict__ vs, __nv_bfloat16* __restrict__ aao)
{
    extern __shared__ __align__(128) char smem[];
    const uint32_t QS = smem_u32(smem);

    const int tid  = threadIdx.x;
    const int lane = tid & 31, wid = tid >> 5;
    const int qt = (int)gridDim.x - 1 - (int)blockIdx.x;   // long tiles first
    const int h  = blockIdx.y, b = blockIdx.z;
    const int q0 = qt * 128;
    const size_t bh = ((size_t)b * NHEAD + h) * SEQ;

    const __nv_bfloat16* qg = qs + (bh + q0) * 128;
    const __nv_bfloat16* kg = ks + bh * 128;
    const __nv_bfloat16* vg = vs + bh * 128;

#pragma unroll
    for (int i = 0; i < 8; i++) {
        int idx = i * 256 + tid;
        int row = idx >> 4, cc = idx & 15;
        cp_async16(QS + row * 256 + ((cc ^ (row & 7)) << 4), qg + row * 128 + cc * 8);
    }
    auto loadKV = [&](int kt, int buf) {
        const uint32_t KB = QS + 32768 + buf * 32768;
        const uint32_t VB = KB + 16384;
        const __nv_bfloat16* kp = kg + (size_t)kt * 64 * 128;
        const __nv_bfloat16* vp = vg + (size_t)kt * 64 * 128;
#pragma unroll
        for (int i = 0; i < 4; i++) {
            int idx = i * 256 + tid;
            int row = idx >> 4, cc = idx & 15;
            uint32_t so = row * 256 + ((cc ^ (row & 7)) << 4);
            cp_async16(KB + so, kp + row * 128 + cc * 8);
            cp_async16(VB + so, vp + row * 128 + cc * 8);
        }
    };
    const int ntiles = 2 * qt + 2;
    loadKV(0, 0); CP_COMMIT();
    loadKV(1, 1); CP_COMMIT();

    float m2[2] = { -1e30f, -1e30f };
    float l2[2] = { 0.f, 0.f };
    float oacc[8][4];
#pragma unroll
    for (int j = 0; j < 8; j++)
#pragma unroll
        for (int e = 0; e < 4; e++) oacc[j][e] = 0.f;

    const int arow = wid * 16 + (lane & 15);

    for (int kt = 0; kt < ntiles; kt++) {
        if (kt + 1 < ntiles) { CP_WAIT(1); } else { CP_WAIT(0); }
        __syncthreads();
        const uint32_t KB = QS + 32768 + (kt & 1) * 32768;
        const uint32_t VB = KB + 16384;

        float sacc[8][4];
#pragma unroll
        for (int j = 0; j < 8; j++)
#pragma unroll
            for (int e = 0; e < 4; e++) sacc[j][e] = 0.f;

#pragma unroll
        for (int s = 0; s < 4; s++) {
            uint32_t ah[4], al[4];
            const int ca = s * 2 + (lane >> 4);
            ldmx4(QS + arow * 256 + (((ca     ) ^ (arow & 7)) << 4), ah[0], ah[1], ah[2], ah[3]);
            ldmx4(QS + arow * 256 + (((ca +  8) ^ (arow & 7)) << 4), al[0], al[1], al[2], al[3]);
            uint32_t bh_[8][2], bl_[8][2];
            const int rb = (lane & 7) + ((lane >> 4) << 3);
            const int cb = s * 2 + ((lane >> 3) & 1);
#pragma unroll
            for (int g = 0; g < 4; g++) {
                const int r = g * 16 + rb;
                uint32_t r0, r1, r2, r3;
                ldmx4(KB + r * 256 + (((cb    ) ^ (r & 7)) << 4), r0, r1, r2, r3);
                bh_[2*g][0] = r0; bh_[2*g][1] = r1; bh_[2*g+1][0] = r2; bh_[2*g+1][1] = r3;
                ldmx4(KB + r * 256 + (((cb + 8) ^ (r & 7)) << 4), r0, r1, r2, r3);
                bl_[2*g][0] = r0; bl_[2*g][1] = r1; bl_[2*g+1][0] = r2; bl_[2*g+1][1] = r3;
            }
#pragma unroll
            for (int j = 0; j < 8; j++) {
                mma_bf16(sacc[j], ah[0], ah[1], ah[2], ah[3], bh_[j][0], bh_[j][1]);
                mma_bf16(sacc[j], ah[0], ah[1], ah[2], ah[3], bl_[j][0], bl_[j][1]);
                mma_bf16(sacc[j], al[0], al[1], al[2], al[3], bh_[j][0], bh_[j][1]);
            }
        }

        if (kt >= 2 * qt) {
            const int k0 = kt * 64;
            const int qr = q0 + wid * 16 + (lane >> 2);
#pragma unroll
            for (int j = 0; j < 8; j++) {
                const int kc = k0 + j * 8 + (lane & 3) * 2;
                if (kc     > qr)     sacc[j][0] = -1e30f;
                if (kc + 1 > qr)     sacc[j][1] = -1e30f;
                if (kc     > qr + 8) sacc[j][2] = -1e30f;
                if (kc + 1 > qr + 8) sacc[j][3] = -1e30f;
            }
        }

        uint32_t phi[8][2], plo[8][2];
#pragma unroll
        for (int hf = 0; hf < 2; hf++) {
            float mx = -1e30f;
#pragma unroll
            for (int j = 0; j < 8; j++)
                mx = fmaxf(mx, fmaxf(sacc[j][hf*2], sacc[j][hf*2+1]));
            mx = fmaxf(mx, __shfl_xor_sync(0xffffffffu, mx, 1));
            mx = fmaxf(mx, __shfl_xor_sync(0xffffffffu, mx, 2));
            const float newm  = fmaxf(m2[hf], mx);
            const float alpha = exp2_poly(m2[hf] - newm);
            float sum = 0.f;
#pragma unroll
            for (int j = 0; j < 8; j++) {
                float p0 = exp2_poly(sacc[j][hf*2]   - newm);
                float p1 = exp2_poly(sacc[j][hf*2+1] - newm);
                sum += p0 + p1;
                float h0, h1;
                phi[j][hf] = pack_hi(p0, p1, h0, h1);
                plo[j][hf] = pack_bf2(p0 - h0, p1 - h1);
            }
            sum += __shfl_xor_sync(0xffffffffu, sum, 1);
            sum += __shfl_xor_sync(0xffffffffu, sum, 2);
            l2[hf] = l2[hf] * alpha + sum;
            m2[hf] = newm;
#pragma unroll
            for (int j = 0; j < 8; j++) {
                oacc[j][hf*2]   *= alpha;
                oacc[j][hf*2+1] *= alpha;
            }
        }

#pragma unroll
        for (int s = 0; s < 4; s++) {
            uint32_t pah[4] = { phi[2*s][0], phi[2*s][1], phi[2*s+1][0], phi[2*s+1][1] };
            uint32_t pal[4] = { plo[2*s][0], plo[2*s][1], plo[2*s+1][0], plo[2*s+1][1] };
            const int rv = s * 16 + (lane & 15);
            uint32_t bvh[8][2], bvl[8][2];
#pragma unroll
            for (int np = 0; np < 4; np++) {
                const int cv = np * 2 + (lane >> 4);
                uint32_t r0, r1, r2, r3;
                ldmx4t(VB + rv * 256 + (((cv    ) ^ (rv & 7)) << 4), r0, r1, r2, r3);
                bvh[2*np][0] = r0; bvh[2*np][1] = r1; bvh[2*np+1][0] = r2; bvh[2*np+1][1] = r3;
                ldmx4t(VB + rv * 256 + (((cv + 8) ^ (rv & 7)) << 4), r0, r1, r2, r3);
                bvl[2*np][0] = r0; bvl[2*np][1] = r1; bvl[2*np+1][0] = r2; bvl[2*np+1][1] = r3;
            }
#pragma unroll
            for (int j = 0; j < 8; j++) {
                mma_bf16(oacc[j], pah[0], pah[1], pah[2], pah[3], bvh[j][0], bvh[j][1]);
                mma_bf16(oacc[j], pah[0], pah[1], pah[2], pah[3], bvl[j][0], bvl[j][1]);
                mma_bf16(oacc[j], pal[0], pal[1], pal[2], pal[3], bvh[j][0], bvh[j][1]);
            }
        }

        __syncthreads();
        if (kt + 2 < ntiles) loadKV(kt + 2, kt & 1);
        CP_COMMIT();
    }

    const float inv0 = 1.f / l2[0], inv1 = 1.f / l2[1];
    const int r = lane >> 2, cp2 = (lane & 3) * 2;
#pragma unroll
    for (int j = 0; j < 8; j++) {
        const int col = h * 64 + j * 8 + cp2;
#pragma unroll
        for (int hf = 0; hf < 2; hf++) {
            const float inv = hf ? inv1 : inv0;
            const int m = b * SEQ + q0 + wid * 16 + r + hf * 8;
            const float v0 = oacc[j][hf*2]   * inv;
            const float v1 = oacc[j][hf*2+1] * inv;
            float h0, h1;
            uint32_t hh = pack_hi(v0, v1, h0, h1);
            uint32_t ll = pack_bf2(v0 - h0, v1 - h1);
            uint32_t* row = (uint32_t*)(aao + (size_t)m * GK);
            row[col >> 1]            = hh;
            row[(1024 + col) >> 1]   = hh;
            row[(2048 + col) >> 1]   = ll;
        }
    }
}

// ---------------------------------------------------------------------------
extern "C" void kernel_launch(void* const* d_in, const int* in_sizes, int n_in,
                              void* d_out, int out_size)
{
    const float* x      = (const float*)d_in[0];
    const float* w_attn = (const float*)d_in[2];
    const float* b_attn = (const float*)d_in[3];
    const float* w_proj = (const float*)d_in[4];
    const float* b_proj = (const float*)d_in[5];

    float* out     = (float*)d_out;
    float* present = out + (size_t)M_TOTAL * D_MODEL;

    __nv_bfloat16 *gAx, *gAao, *gBq, *gBp, *gqs, *gks, *gvs;
    cudaGetSymbolAddress((void**)&gAx,  g_Ax);
    cudaGetSymbolAddress((void**)&gAao, g_Aao);
    cudaGetSymbolAddress((void**)&gBq,  g_Bqkv);
    cudaGetSymbolAddress((void**)&gBp,  g_Bprj);
    cudaGetSymbolAddress((void**)&gqs,  g_qs);
    cudaGetSymbolAddress((void**)&gks,  g_ks);
    cudaGetSymbolAddress((void**)&gvs,  g_vs);

    static bool attr_set = false;
    if (!attr_set) {
        cudaFuncSetAttribute(attn_mma,    cudaFuncAttributeMaxDynamicSharedMemorySize, ATTN_SMEM);
        cudaFuncSetAttribute(gemm_mma<1>, cudaFuncAttributeMaxDynamicSharedMemorySize, SMEM_MMA);
        cudaFuncSetAttribute(gemm_mma<0>, cudaFuncAttributeMaxDynamicSharedMemorySize, SMEM_MMA);
        attr_set = true;
    }

    // Prep: split-bf16 operands
    conv_a_kernel<<<(M_TOTAL * 256 + 255) / 256, 256>>>(x, gAx);
    conv_w_kernel<<<dim3(3 * D_MODEL / 32, D_MODEL / 32), dim3(32, 8)>>>(w_attn, gBq, 3 * D_MODEL);
    conv_w_kernel<<<dim3(D_MODEL / 32, D_MODEL / 32), dim3(32, 8)>>>(w_proj, gBp, D_MODEL);

    // QKV GEMM with fused split/scale scatter epilogue
    gemm_mma<1><<<dim3(3 * D_MODEL / 128, M_TOTAL / 128), 256, SMEM_MMA>>>(
        gAx, gBq, b_attn, nullptr, present, 3 * D_MODEL, gqs, gks, gvs);

    // Tensor-core flash attention -> writes split proj input directly
    attn_mma<<<dim3(SEQ / 128, NHEAD, BATCH), 256, ATTN_SMEM>>>(gqs, gks, gvs, gAao);

    // Proj GEMM
    gemm_mma<0><<<dim3(D_MODEL / 128, M_TOTAL / 128), 256, SMEM_MMA>>>(
        gAao, gBp, b_proj, out, nullptr, D_MODEL, nullptr, nullptr, nullptr);
}

// round 7
// speedup vs baseline: 2.8197x; 1.1371x over previous
#include <cuda_runtime.h>
#include <cuda_bf16.h>
#include <math_constants.h>
#include <cstdint>

// Problem constants
#define D_MODEL 1024
#define NHEAD   16
#define DEPTH   64
#define BATCH   2
#define SEQ     2048
#define M_TOTAL (BATCH*SEQ)   // 4096
#define AK      2048          // dedup split layout: [row][32 chunks][hi32|lo32]
#define QSCALE  (0.125f * 1.4426950408889634f)   // 1/sqrt(64) * log2(e)

// ---------------------------------------------------------------------------
// Scratch (device globals — no allocation allowed)
// ---------------------------------------------------------------------------
__device__ __nv_bfloat16 g_qs [(size_t)BATCH*NHEAD*SEQ*128];  // q split, pre-scaled
__device__ __nv_bfloat16 g_ks [(size_t)BATCH*NHEAD*SEQ*128];  // k split
__device__ __nv_bfloat16 g_vs [(size_t)BATCH*NHEAD*SEQ*128];  // v split
__device__ __nv_bfloat16 g_Ax [(size_t)M_TOTAL*AK];           // x split
__device__ __nv_bfloat16 g_Aao[(size_t)M_TOTAL*AK];           // attn-out split
__device__ __nv_bfloat16 g_Bqkv[(size_t)3*D_MODEL*AK];        // w_attn^T split
__device__ __nv_bfloat16 g_Bprj[(size_t)D_MODEL*AK];          // w_proj^T split

// ---------------------------------------------------------------------------
// Helpers
// ---------------------------------------------------------------------------
__device__ __forceinline__ uint32_t smem_u32(const void* p) {
    uint32_t a;
    asm("{ .reg .u64 t; cvta.to.shared.u64 t, %1; cvt.u32.u64 %0, t; }" : "=r"(a) : "l"(p));
    return a;
}
__device__ __forceinline__ void cp_async16(uint32_t saddr, const void* gptr) {
    asm volatile("cp.async.cg.shared.global [%0], [%1], 16;" :: "r"(saddr), "l"(gptr));
}
#define CP_COMMIT() asm volatile("cp.async.commit_group;" ::: "memory")
#define CP_WAIT(n)  asm volatile("cp.async.wait_group %0;" :: "n"(n) : "memory")

__device__ __forceinline__ void ldmx4(uint32_t addr, uint32_t& r0, uint32_t& r1,
                                      uint32_t& r2, uint32_t& r3) {
    asm volatile("ldmatrix.sync.aligned.m8n8.x4.shared.b16 {%0,%1,%2,%3}, [%4];"
                 : "=r"(r0), "=r"(r1), "=r"(r2), "=r"(r3) : "r"(addr));
}
__device__ __forceinline__ void ldmx4t(uint32_t addr, uint32_t& r0, uint32_t& r1,
                                       uint32_t& r2, uint32_t& r3) {
    asm volatile("ldmatrix.sync.aligned.m8n8.x4.trans.shared.b16 {%0,%1,%2,%3}, [%4];"
                 : "=r"(r0), "=r"(r1), "=r"(r2), "=r"(r3) : "r"(addr));
}
__device__ __forceinline__ void mma_bf16(float c[4], uint32_t a0, uint32_t a1,
                                         uint32_t a2, uint32_t a3,
                                         uint32_t b0, uint32_t b1) {
    asm volatile("mma.sync.aligned.m16n8k16.row.col.f32.bf16.bf16.f32 "
                 "{%0,%1,%2,%3}, {%4,%5,%6,%7}, {%8,%9}, {%0,%1,%2,%3};"
                 : "+f"(c[0]), "+f"(c[1]), "+f"(c[2]), "+f"(c[3])
                 : "r"(a0), "r"(a1), "r"(a2), "r"(a3), "r"(b0), "r"(b1));
}

// FMA-pipe exp2 (degree-6; rel err < 3e-6). Inputs expected <= 0.
__device__ __forceinline__ float exp2_poly(float t) {
    t = fmaxf(t, -125.0f);
    float n = floorf(t);
    float f = t - n;
    float p = 1.5403530393381608e-4f;
    p = fmaf(p, f, 1.3333558146428443e-3f);
    p = fmaf(p, f, 9.6181291076284770e-3f);
    p = fmaf(p, f, 5.5504108664821580e-2f);
    p = fmaf(p, f, 2.4022650695910070e-1f);
    p = fmaf(p, f, 6.9314718055994530e-1f);
    p = fmaf(p, f, 1.0f);
    return p * __int_as_float(((int)n + 127) << 23);
}

__device__ __forceinline__ uint32_t pack_hi(float a, float b, float& ha, float& hb) {
    __nv_bfloat162 hh = __floats2bfloat162_rn(a, b);
    ha = __bfloat162float(hh.x);
    hb = __bfloat162float(hh.y);
    return *(uint32_t*)&hh;
}
__device__ __forceinline__ uint32_t pack_bf2(float a, float b) {
    __nv_bfloat162 hh = __floats2bfloat162_rn(a, b);
    return *(uint32_t*)&hh;
}

// ---------------------------------------------------------------------------
// Prep: x[M,1024] fp32 -> A''[M,2048]: per 32-k chunk, [hi32|lo32]
// ---------------------------------------------------------------------------
__global__ __launch_bounds__(256)
void conv_a_kernel(const float* __restrict__ X, __nv_bfloat16* __restrict__ Ad) {
    int i = blockIdx.x * blockDim.x + threadIdx.x;
    if (i >= M_TOTAL * 256) return;
    int m  = i >> 8;
    int kq = (i & 255) << 2;
    float4 v = ((const float4*)X)[i];
    union { __nv_bfloat16 h[4]; uint2 u; } hi, lo;
    hi.h[0] = __float2bfloat16(v.x); lo.h[0] = __float2bfloat16(v.x - __bfloat162float(hi.h[0]));
    hi.h[1] = __float2bfloat16(v.y); lo.h[1] = __float2bfloat16(v.y - __bfloat162float(hi.h[1]));
    hi.h[2] = __float2bfloat16(v.z); lo.h[2] = __float2bfloat16(v.z - __bfloat162float(hi.h[2]));
    hi.h[3] = __float2bfloat16(v.w); lo.h[3] = __float2bfloat16(v.w - __bfloat162float(hi.h[3]));
    const int ci = kq >> 5, j = kq & 31;
    size_t base = (size_t)m * AK + ci * 64 + j;
    *(uint2*)(Ad + base)      = hi.u;
    *(uint2*)(Ad + base + 32) = lo.u;
}

// ---------------------------------------------------------------------------
// Prep: w[1024,N] fp32 -> B''[N,2048] (transposed; chunk layout [hi32|lo32])
// ---------------------------------------------------------------------------
__global__ __launch_bounds__(256)
void conv_w_kernel(const float* __restrict__ W, __nv_bfloat16* __restrict__ Bd, int N) {
    __shared__ float t[32][33];
    const int k0 = blockIdx.y * 32, n0 = blockIdx.x * 32;
    for (int r = threadIdx.y; r < 32; r += 8)
        t[r][threadIdx.x] = W[(size_t)(k0 + r) * N + n0 + threadIdx.x];
    __syncthreads();
    for (int r = threadIdx.y; r < 32; r += 8) {
        const int n = n0 + r, k = k0 + threadIdx.x;
        float v = t[threadIdx.x][r];
        __nv_bfloat16 h  = __float2bfloat16(v);
        __nv_bfloat16 lo = __float2bfloat16(v - __bfloat162float(h));
        __nv_bfloat16* row = Bd + (size_t)n * AK;
        const int ci = k >> 5, j = k & 31;
        row[ci * 64 + j]      = h;
        row[ci * 64 + 32 + j] = lo;
    }
}

// ---------------------------------------------------------------------------
// mma.sync bf16 split GEMM: 3 terms from dedup [hi32|lo32] chunks.
// 128x128 tile, 32 real-k per stage (32KB), 3 stages, 2 CTAs/SM.
// ---------------------------------------------------------------------------
#define NKIT 32               // 1024 real k / 32
#define STG_BYTES 32768       // A 16KB + B 16KB
#define SMEM_MMA (3*STG_BYTES)

template<int QKV>
__global__ __launch_bounds__(256, 2)
void gemm_mma(const __nv_bfloat16* __restrict__ A, const __nv_bfloat16* __restrict__ B,
              const float* __restrict__ bias, float* __restrict__ out0,
              float* __restrict__ present, int N,
              __nv_bfloat16* __restrict__ qsp, __nv_bfloat16* __restrict__ ksp,
              __nv_bfloat16* __restrict__ vsp)
{
    extern __shared__ __align__(128) char smem[];
    const uint32_t sbase = smem_u32(smem);

    const int tid  = threadIdx.x;
    const int lane = tid & 31, wid = tid >> 5;
    const int m0 = blockIdx.y * 128, n0 = blockIdx.x * 128;
    const int wm0 = (wid >> 2) * 64;
    const int wn0 = (wid & 3) * 32;

    const int lrow = tid >> 1;
    const int lc0  = (tid & 1) * 4;
    const __nv_bfloat16* aG = A + (size_t)(m0 + lrow) * AK;
    const __nv_bfloat16* bG = B + (size_t)(n0 + lrow) * AK;
    const uint32_t wOffBase = (uint32_t)lrow * 128;

    float c[4][4][4];
#pragma unroll
    for (int mi = 0; mi < 4; mi++)
#pragma unroll
        for (int ni = 0; ni < 4; ni++)
#pragma unroll
            for (int e = 0; e < 4; e++) c[mi][ni][e] = 0.f;

    auto load_stage = [&](int st, int kt) {
        const uint32_t s0 = sbase + st * STG_BYTES;
        const __nv_bfloat16* ag = aG + kt * 64;   // one [hi32|lo32] chunk = 128B
        const __nv_bfloat16* bg = bG + kt * 64;
#pragma unroll
        for (int i = 0; i < 4; i++) {
            uint32_t wo = wOffBase + (uint32_t)(((lc0 + i) ^ (lrow & 7)) << 4);
            cp_async16(s0 + wo,         ag + (lc0 + i) * 8);
            cp_async16(s0 + 16384 + wo, bg + (lc0 + i) * 8);
        }
    };

    auto compute = [&](int st) {
        const uint32_t sA = sbase + st * STG_BYTES;
        const uint32_t sB = sA + 16384;
#pragma unroll
        for (int ks = 0; ks < 2; ks++) {
            uint32_t ahi[4][4], alo[4][4], bhi[4][2], blo[4][2];
            const int ca = ks * 2 + (lane >> 4);     // hi cols 0..3
#pragma unroll
            for (int mi = 0; mi < 4; mi++) {
                const int r = wm0 + mi * 16 + (lane & 15);
                ldmx4(sA + r * 128 + ((( ca      ^ (r & 7))) << 4),
                      ahi[mi][0], ahi[mi][1], ahi[mi][2], ahi[mi][3]);
                ldmx4(sA + r * 128 + ((((ca + 4) ^ (r & 7))) << 4),
                      alo[mi][0], alo[mi][1], alo[mi][2], alo[mi][3]);
            }
            const int cb = ks * 2 + ((lane >> 3) & 1);
            const int rbase = wn0 + (lane & 7) + ((lane >> 4) << 3);
#pragma unroll
            for (int np = 0; np < 2; np++) {
                const int r = rbase + np * 16;
                uint32_t r0, r1, r2, r3;
                ldmx4(sB + r * 128 + ((( cb      ^ (r & 7))) << 4), r0, r1, r2, r3);
                bhi[np * 2][0] = r0;     bhi[np * 2][1] = r1;
                bhi[np * 2 + 1][0] = r2; bhi[np * 2 + 1][1] = r3;
                ldmx4(sB + r * 128 + ((((cb + 4) ^ (r & 7))) << 4), r0, r1, r2, r3);
                blo[np * 2][0] = r0;     blo[np * 2][1] = r1;
                blo[np * 2 + 1][0] = r2; blo[np * 2 + 1][1] = r3;
            }
#pragma unroll
            for (int mi = 0; mi < 4; mi++)
#pragma unroll
                for (int ni = 0; ni < 4; ni++)
                    mma_bf16(c[mi][ni], ahi[mi][0], ahi[mi][1], ahi[mi][2], ahi[mi][3],
                             bhi[ni][0], bhi[ni][1]);
#pragma unroll
            for (int mi = 0; mi < 4; mi++)
#pragma unroll
                for (int ni = 0; ni < 4; ni++)
                    mma_bf16(c[mi][ni], ahi[mi][0], ahi[mi][1], ahi[mi][2], ahi[mi][3],
                             blo[ni][0], blo[ni][1]);
#pragma unroll
            for (int mi = 0; mi < 4; mi++)
#pragma unroll
                for (int ni = 0; ni < 4; ni++)
                    mma_bf16(c[mi][ni], alo[mi][0], alo[mi][1], alo[mi][2], alo[mi][3],
                             bhi[ni][0], bhi[ni][1]);
        }
    };

    load_stage(0, 0); CP_COMMIT();
    load_stage(1, 1); CP_COMMIT();

    for (int kt = 0; kt < NKIT; kt++) {
        CP_WAIT(1);
        __syncthreads();
        if (kt + 2 < NKIT) load_stage((kt + 2) % 3, kt + 2);
        CP_COMMIT();
        compute(kt % 3);
    }

    const int gr = lane >> 2, tc = lane & 3;
#pragma unroll
    for (int mi = 0; mi < 4; mi++) {
#pragma unroll
        for (int rr = 0; rr < 2; rr++) {
            const int m = m0 + wm0 + mi * 16 + gr + rr * 8;
            const int bidx = m >> 11, s = m & (SEQ - 1);
#pragma unroll
            for (int ni = 0; ni < 4; ni++) {
                const int n = n0 + wn0 + ni * 8 + tc * 2;
                float2 bb = *(const float2*)(bias + n);
                float2 v;
                v.x = c[mi][ni][rr * 2 + 0] + bb.x;
                v.y = c[mi][ni][rr * 2 + 1] + bb.y;
                if (QKV == 0) {
                    *(float2*)&out0[(size_t)m * N + n] = v;
                } else {
                    const int tsr = n >> 10;           // 0=q 1=k 2=v
                    const int nn  = n & (D_MODEL - 1);
                    const int h   = nn >> 6, d = nn & 63;
                    const size_t rowi = ((size_t)bidx * NHEAD + h) * SEQ + s;
                    if (tsr == 0) {
                        float q0v = v.x * QSCALE, q1v = v.y * QSCALE;
                        float h0, h1;
                        uint32_t hh = pack_hi(q0v, q1v, h0, h1);
                        uint32_t ll = pack_bf2(q0v - h0, q1v - h1);
                        uint32_t* qrow = (uint32_t*)(qsp + rowi * 128);
                        qrow[d >> 1]        = hh;
                        qrow[32 + (d >> 1)] = ll;
                    } else {
                        float* dst = present +
                            ((((size_t)(bidx * 2 + (tsr - 1)) * NHEAD + h) * SEQ + s) * DEPTH + d);
                        *(float2*)dst = v;
                        float h0, h1;
                        uint32_t hh = pack_hi(v.x, v.y, h0, h1);
                        uint32_t ll = pack_bf2(v.x - h0, v.y - h1);
                        uint32_t* krow = (uint32_t*)((tsr == 1 ? ksp : vsp) + rowi * 128);
                        krow[d >> 1]        = hh;
                        krow[32 + (d >> 1)] = ll;
                    }
                }
            }
        }
    }
}

// ---------------------------------------------------------------------------
// Tensor-core flash attention (split-bf16, exact to ~1.5e-5).
// CTA: 256 threads (8 warps), Br=128 (16 q-rows/warp), Bc=64.
// ---------------------------------------------------------------------------
#define ATTN_SMEM (32768 + 2*32768)   // Q 32KB + 2 x (K 16KB + V 16KB)

__global__ __launch_bounds__(256, 1)
void attn_mma(const __nv_bfloat16* __restrict__ qs, const __nv_bfloat16* __restrict__ ks,
              const __nv_bfloat16* __restrict__ vs, __nv_bfloat16* __restrict__ aao)
{
    extern __shared__ __align__(128) char smem[];
    const uint32_t QS = smem_u32(smem);

    const int tid  = threadIdx.x;
    const int lane = tid & 31, wid = tid >> 5;
    const int qt = (int)gridDim.x - 1 - (int)blockIdx.x;   // long tiles first
    const int h  = blockIdx.y, b = blockIdx.z;
    const int q0 = qt * 128;
    const size_t bh = ((size_t)b * NHEAD + h) * SEQ;

    const __nv_bfloat16* qg = qs + (bh + q0) * 128;
    const __nv_bfloat16* kg = ks + bh * 128;
    const __nv_bfloat16* vg = vs + bh * 128;

#pragma unroll
    for (int i = 0; i < 8; i++) {
        int idx = i * 256 + tid;
        int row = idx >> 4, cc = idx & 15;
        cp_async16(QS + row * 256 + ((cc ^ (row & 7)) << 4), qg + row * 128 + cc * 8);
    }
    auto loadKV = [&](int kt, int buf) {
        const uint32_t KB = QS + 32768 + buf * 32768;
        const uint32_t VB = KB + 16384;
        const __nv_bfloat16* kp = kg + (size_t)kt * 64 * 128;
        const __nv_bfloat16* vp = vg + (size_t)kt * 64 * 128;
#pragma unroll
        for (int i = 0; i < 4; i++) {
            int idx = i * 256 + tid;
            int row = idx >> 4, cc = idx & 15;
            uint32_t so = row * 256 + ((cc ^ (row & 7)) << 4);
            cp_async16(KB + so, kp + row * 128 + cc * 8);
            cp_async16(VB + so, vp + row * 128 + cc * 8);
        }
    };
    const int ntiles = 2 * qt + 2;
    loadKV(0, 0); CP_COMMIT();
    loadKV(1, 1); CP_COMMIT();

    float m2[2] = { -1e30f, -1e30f };
    float l2[2] = { 0.f, 0.f };
    float oacc[8][4];
#pragma unroll
    for (int j = 0; j < 8; j++)
#pragma unroll
        for (int e = 0; e < 4; e++) oacc[j][e] = 0.f;

    const int arow = wid * 16 + (lane & 15);

    for (int kt = 0; kt < ntiles; kt++) {
        if (kt + 1 < ntiles) { CP_WAIT(1); } else { CP_WAIT(0); }
        __syncthreads();
        const uint32_t KB = QS + 32768 + (kt & 1) * 32768;
        const uint32_t VB = KB + 16384;

        float sacc[8][4];
#pragma unroll
        for (int j = 0; j < 8; j++)
#pragma unroll
            for (int e = 0; e < 4; e++) sacc[j][e] = 0.f;

#pragma unroll
        for (int s = 0; s < 4; s++) {
            uint32_t ah[4], al[4];
            const int ca = s * 2 + (lane >> 4);
            ldmx4(QS + arow * 256 + (((ca     ) ^ (arow & 7)) << 4), ah[0], ah[1], ah[2], ah[3]);
            ldmx4(QS + arow * 256 + (((ca +  8) ^ (arow & 7)) << 4), al[0], al[1], al[2], al[3]);
            uint32_t bh_[8][2], bl_[8][2];
            const int rb = (lane & 7) + ((lane >> 4) << 3);
            const int cb = s * 2 + ((lane >> 3) & 1);
#pragma unroll
            for (int g = 0; g < 4; g++) {
                const int r = g * 16 + rb;
                uint32_t r0, r1, r2, r3;
                ldmx4(KB + r * 256 + (((cb    ) ^ (r & 7)) << 4), r0, r1, r2, r3);
                bh_[2*g][0] = r0; bh_[2*g][1] = r1; bh_[2*g+1][0] = r2; bh_[2*g+1][1] = r3;
                ldmx4(KB + r * 256 + (((cb + 8) ^ (r & 7)) << 4), r0, r1, r2, r3);
                bl_[2*g][0] = r0; bl_[2*g][1] = r1; bl_[2*g+1][0] = r2; bl_[2*g+1][1] = r3;
            }
#pragma unroll
            for (int j = 0; j < 8; j++) {
                mma_bf16(sacc[j], ah[0], ah[1], ah[2], ah[3], bh_[j][0], bh_[j][1]);
                mma_bf16(sacc[j], ah[0], ah[1], ah[2], ah[3], bl_[j][0], bl_[j][1]);
                mma_bf16(sacc[j], al[0], al[1], al[2], al[3], bh_[j][0], bh_[j][1]);
            }
        }

        if (kt >= 2 * qt) {
            const int k0 = kt * 64;
            const int qr = q0 + wid * 16 + (lane >> 2);
#pragma unroll
            for (int j = 0; j < 8; j++) {
                const int kc = k0 + j * 8 + (lane & 3) * 2;
                if (kc     > qr)     sacc[j][0] = -1e30f;
                if (kc + 1 > qr)     sacc[j][1] = -1e30f;
                if (kc     > qr + 8) sacc[j][2] = -1e30f;
                if (kc + 1 > qr + 8) sacc[j][3] = -1e30f;
            }
        }

        uint32_t phi[8][2], plo[8][2];
#pragma unroll
        for (int hf = 0; hf < 2; hf++) {
            float mx = -1e30f;
#pragma unroll
            for (int j = 0; j < 8; j++)
                mx = fmaxf(mx, fmaxf(sacc[j][hf*2], sacc[j][hf*2+1]));
            mx = fmaxf(mx, __shfl_xor_sync(0xffffffffu, mx, 1));
            mx = fmaxf(mx, __shfl_xor_sync(0xffffffffu, mx, 2));
            const float newm  = fmaxf(m2[hf], mx);
            const float alpha = exp2_poly(m2[hf] - newm);
            float sum = 0.f;
#pragma unroll
            for (int j = 0; j < 8; j++) {
                float p0 = exp2_poly(sacc[j][hf*2]   - newm);
                float p1 = exp2_poly(sacc[j][hf*2+1] - newm);
                sum += p0 + p1;
                float h0, h1;
                phi[j][hf] = pack_hi(p0, p1, h0, h1);
                plo[j][hf] = pack_bf2(p0 - h0, p1 - h1);
            }
            sum += __shfl_xor_sync(0xffffffffu, sum, 1);
            sum += __shfl_xor_sync(0xffffffffu, sum, 2);
            l2[hf] = l2[hf] * alpha + sum;
            m2[hf] = newm;
#pragma unroll
            for (int j = 0; j < 8; j++) {
                oacc[j][hf*2]   *= alpha;
                oacc[j][hf*2+1] *= alpha;
            }
        }

#pragma unroll
        for (int s = 0; s < 4; s++) {
            uint32_t pah[4] = { phi[2*s][0], phi[2*s][1], phi[2*s+1][0], phi[2*s+1][1] };
            uint32_t pal[4] = { plo[2*s][0], plo[2*s][1], plo[2*s+1][0], plo[2*s+1][1] };
            const int rv = s * 16 + (lane & 15);
            uint32_t bvh[8][2], bvl[8][2];
#pragma unroll
            for (int np = 0; np < 4; np++) {
                const int cv = np * 2 + (lane >> 4);
                uint32_t r0, r1, r2, r3;
                ldmx4t(VB + rv * 256 + (((cv    ) ^ (rv & 7)) << 4), r0, r1, r2, r3);
                bvh[2*np][0] = r0; bvh[2*np][1] = r1; bvh[2*np+1][0] = r2; bvh[2*np+1][1] = r3;
                ldmx4t(VB + rv * 256 + (((cv + 8) ^ (rv & 7)) << 4), r0, r1, r2, r3);
                bvl[2*np][0] = r0; bvl[2*np][1] = r1; bvl[2*np+1][0] = r2; bvl[2*np+1][1] = r3;
            }
#pragma unroll
            for (int j = 0; j < 8; j++) {
                mma_bf16(oacc[j], pah[0], pah[1], pah[2], pah[3], bvh[j][0], bvh[j][1]);
                mma_bf16(oacc[j], pah[0], pah[1], pah[2], pah[3], bvl[j][0], bvl[j][1]);
                mma_bf16(oacc[j], pal[0], pal[1], pal[2], pal[3], bvh[j][0], bvh[j][1]);
            }
        }

        __syncthreads();
        if (kt + 2 < ntiles) loadKV(kt + 2, kt & 1);
        CP_COMMIT();
    }

    // epilogue: write proj input in dedup layout [m][chunk32][hi32|lo32]
    const float inv0 = 1.f / l2[0], inv1 = 1.f / l2[1];
    const int r = lane >> 2, cp2 = (lane & 3) * 2;
#pragma unroll
    for (int j = 0; j < 8; j++) {
        const int col = h * 64 + j * 8 + cp2;
        const int ci = col >> 5, jj = col & 31;
#pragma unroll
        for (int hf = 0; hf < 2; hf++) {
            const float inv = hf ? inv1 : inv0;
            const int m = b * SEQ + q0 + wid * 16 + r + hf * 8;
            const float v0 = oacc[j][hf*2]   * inv;
            const float v1 = oacc[j][hf*2+1] * inv;
            float h0, h1;
            uint32_t hh = pack_hi(v0, v1, h0, h1);
            uint32_t ll = pack_bf2(v0 - h0, v1 - h1);
            uint32_t* row = (uint32_t*)(aao + (size_t)m * AK);
            row[ci * 32 + (jj >> 1)]      = hh;
            row[ci * 32 + 16 + (jj >> 1)] = ll;
        }
    }
}

// ---------------------------------------------------------------------------
extern "C" void kernel_launch(void* const* d_in, const int* in_sizes, int n_in,
                              void* d_out, int out_size)
{
    const float* x      = (const float*)d_in[0];
    const float* w_attn = (const float*)d_in[2];
    const float* b_attn = (const float*)d_in[3];
    const float* w_proj = (const float*)d_in[4];
    const float* b_proj = (const float*)d_in[5];

    float* out     = (float*)d_out;
    float* present = out + (size_t)M_TOTAL * D_MODEL;

    __nv_bfloat16 *gAx, *gAao, *gBq, *gBp, *gqs, *gks, *gvs;
    cudaGetSymbolAddress((void**)&gAx,  g_Ax);
    cudaGetSymbolAddress((void**)&gAao, g_Aao);
    cudaGetSymbolAddress((void**)&gBq,  g_Bqkv);
    cudaGetSymbolAddress((void**)&gBp,  g_Bprj);
    cudaGetSymbolAddress((void**)&gqs,  g_qs);
    cudaGetSymbolAddress((void**)&gks,  g_ks);
    cudaGetSymbolAddress((void**)&gvs,  g_vs);

    static bool attr_set = false;
    if (!attr_set) {
        cudaFuncSetAttribute(attn_mma,    cudaFuncAttributeMaxDynamicSharedMemorySize, ATTN_SMEM);
        cudaFuncSetAttribute(gemm_mma<1>, cudaFuncAttributeMaxDynamicSharedMemorySize, SMEM_MMA);
        cudaFuncSetAttribute(gemm_mma<0>, cudaFuncAttributeMaxDynamicSharedMemorySize, SMEM_MMA);
        attr_set = true;
    }

    // Prep: split-bf16 operands (dedup layout)
    conv_a_kernel<<<(M_TOTAL * 256 + 255) / 256, 256>>>(x, gAx);
    conv_w_kernel<<<dim3(3 * D_MODEL / 32, D_MODEL / 32), dim3(32, 8)>>>(w_attn, gBq, 3 * D_MODEL);
    conv_w_kernel<<<dim3(D_MODEL / 32, D_MODEL / 32), dim3(32, 8)>>>(w_proj, gBp, D_MODEL);

    // QKV GEMM with fused split/scale scatter epilogue
    gemm_mma<1><<<dim3(3 * D_MODEL / 128, M_TOTAL / 128), 256, SMEM_MMA>>>(
        gAx, gBq, b_attn, nullptr, present, 3 * D_MODEL, gqs, gks, gvs);

    // Tensor-core flash attention -> writes split proj input directly
    attn_mma<<<dim3(SEQ / 128, NHEAD, BATCH), 256, ATTN_SMEM>>>(gqs, gks, gvs, gAao);

    // Proj GEMM
    gemm_mma<0><<<dim3(D_MODEL / 128, M_TOTAL / 128), 256, SMEM_MMA>>>(
        gAao, gBp, b_proj, out, nullptr, D_MODEL, nullptr, nullptr, nullptr);
}

// round 8
// speedup vs baseline: 3.1043x; 1.1009x over previous
#include <cuda_runtime.h>
#include <cuda_bf16.h>
#include <math_constants.h>
#include <cstdint>

// Problem constants
#define D_MODEL 1024
#define NHEAD   16
#define DEPTH   64
#define BATCH   2
#define SEQ     2048
#define M_TOTAL (BATCH*SEQ)   // 4096
#define AK      2048          // dedup split layout: [row][32 chunks][hi32|lo32]
#define QSCALE  (0.125f * 1.4426950408889634f)   // 1/sqrt(64) * log2(e)

// ---------------------------------------------------------------------------
// Scratch (device globals — no allocation allowed)
// ---------------------------------------------------------------------------
__device__ __nv_bfloat16 g_qs [(size_t)BATCH*NHEAD*SEQ*128];  // q split, pre-scaled
__device__ __nv_bfloat16 g_ks [(size_t)BATCH*NHEAD*SEQ*128];  // k split
__device__ __nv_bfloat16 g_vs [(size_t)BATCH*NHEAD*SEQ*128];  // v split
__device__ __nv_bfloat16 g_Ax [(size_t)M_TOTAL*AK];           // x split
__device__ __nv_bfloat16 g_Aao[(size_t)M_TOTAL*AK];           // attn-out split
__device__ __nv_bfloat16 g_Bqkv[(size_t)3*D_MODEL*AK];        // w_attn^T split
__device__ __nv_bfloat16 g_Bprj[(size_t)D_MODEL*AK];          // w_proj^T split

// ---------------------------------------------------------------------------
// Helpers
// ---------------------------------------------------------------------------
__device__ __forceinline__ uint32_t smem_u32(const void* p) {
    uint32_t a;
    asm("{ .reg .u64 t; cvta.to.shared.u64 t, %1; cvt.u32.u64 %0, t; }" : "=r"(a) : "l"(p));
    return a;
}
__device__ __forceinline__ void cp_async16(uint32_t saddr, const void* gptr) {
    asm volatile("cp.async.cg.shared.global [%0], [%1], 16;" :: "r"(saddr), "l"(gptr));
}
#define CP_COMMIT() asm volatile("cp.async.commit_group;" ::: "memory")
#define CP_WAIT(n)  asm volatile("cp.async.wait_group %0;" :: "n"(n) : "memory")

__device__ __forceinline__ void ldmx4(uint32_t addr, uint32_t& r0, uint32_t& r1,
                                      uint32_t& r2, uint32_t& r3) {
    asm volatile("ldmatrix.sync.aligned.m8n8.x4.shared.b16 {%0,%1,%2,%3}, [%4];"
                 : "=r"(r0), "=r"(r1), "=r"(r2), "=r"(r3) : "r"(addr));
}
__device__ __forceinline__ void ldmx4t(uint32_t addr, uint32_t& r0, uint32_t& r1,
                                       uint32_t& r2, uint32_t& r3) {
    asm volatile("ldmatrix.sync.aligned.m8n8.x4.trans.shared.b16 {%0,%1,%2,%3}, [%4];"
                 : "=r"(r0), "=r"(r1), "=r"(r2), "=r"(r3) : "r"(addr));
}
__device__ __forceinline__ void mma_bf16(float c[4], uint32_t a0, uint32_t a1,
                                         uint32_t a2, uint32_t a3,
                                         uint32_t b0, uint32_t b1) {
    asm volatile("mma.sync.aligned.m16n8k16.row.col.f32.bf16.bf16.f32 "
                 "{%0,%1,%2,%3}, {%4,%5,%6,%7}, {%8,%9}, {%0,%1,%2,%3};"
                 : "+f"(c[0]), "+f"(c[1]), "+f"(c[2]), "+f"(c[3])
                 : "r"(a0), "r"(a1), "r"(a2), "r"(a3), "r"(b0), "r"(b1));
}

// FMA-pipe exp2 (degree-6; rel err < 3e-6). Inputs expected <= 0.
__device__ __forceinline__ float exp2_poly(float t) {
    t = fmaxf(t, -125.0f);
    float n = floorf(t);
    float f = t - n;
    float p = 1.5403530393381608e-4f;
    p = fmaf(p, f, 1.3333558146428443e-3f);
    p = fmaf(p, f, 9.6181291076284770e-3f);
    p = fmaf(p, f, 5.5504108664821580e-2f);
    p = fmaf(p, f, 2.4022650695910070e-1f);
    p = fmaf(p, f, 6.9314718055994530e-1f);
    p = fmaf(p, f, 1.0f);
    return p * __int_as_float(((int)n + 127) << 23);
}

__device__ __forceinline__ uint32_t pack_hi(float a, float b, float& ha, float& hb) {
    __nv_bfloat162 hh = __floats2bfloat162_rn(a, b);
    ha = __bfloat162float(hh.x);
    hb = __bfloat162float(hh.y);
    return *(uint32_t*)&hh;
}
__device__ __forceinline__ uint32_t pack_bf2(float a, float b) {
    __nv_bfloat162 hh = __floats2bfloat162_rn(a, b);
    return *(uint32_t*)&hh;
}

// ---------------------------------------------------------------------------
// Prep: x[M,1024] fp32 -> A''[M,2048]: per 32-k chunk, [hi32|lo32]
// ---------------------------------------------------------------------------
__global__ __launch_bounds__(256)
void conv_a_kernel(const float* __restrict__ X, __nv_bfloat16* __restrict__ Ad) {
    int i = blockIdx.x * blockDim.x + threadIdx.x;
    if (i >= M_TOTAL * 256) return;
    int m  = i >> 8;
    int kq = (i & 255) << 2;
    float4 v = ((const float4*)X)[i];
    union { __nv_bfloat16 h[4]; uint2 u; } hi, lo;
    hi.h[0] = __float2bfloat16(v.x); lo.h[0] = __float2bfloat16(v.x - __bfloat162float(hi.h[0]));
    hi.h[1] = __float2bfloat16(v.y); lo.h[1] = __float2bfloat16(v.y - __bfloat162float(hi.h[1]));
    hi.h[2] = __float2bfloat16(v.z); lo.h[2] = __float2bfloat16(v.z - __bfloat162float(hi.h[2]));
    hi.h[3] = __float2bfloat16(v.w); lo.h[3] = __float2bfloat16(v.w - __bfloat162float(hi.h[3]));
    const int ci = kq >> 5, j = kq & 31;
    size_t base = (size_t)m * AK + ci * 64 + j;
    *(uint2*)(Ad + base)      = hi.u;
    *(uint2*)(Ad + base + 32) = lo.u;
}

// ---------------------------------------------------------------------------
// Prep: w[1024,N] fp32 -> B''[N,2048] (transposed; chunk layout [hi32|lo32])
// ---------------------------------------------------------------------------
__global__ __launch_bounds__(256)
void conv_w_kernel(const float* __restrict__ W, __nv_bfloat16* __restrict__ Bd, int N) {
    __shared__ float t[32][33];
    const int k0 = blockIdx.y * 32, n0 = blockIdx.x * 32;
    for (int r = threadIdx.y; r < 32; r += 8)
        t[r][threadIdx.x] = W[(size_t)(k0 + r) * N + n0 + threadIdx.x];
    __syncthreads();
    for (int r = threadIdx.y; r < 32; r += 8) {
        const int n = n0 + r, k = k0 + threadIdx.x;
        float v = t[threadIdx.x][r];
        __nv_bfloat16 h  = __float2bfloat16(v);
        __nv_bfloat16 lo = __float2bfloat16(v - __bfloat162float(h));
        __nv_bfloat16* row = Bd + (size_t)n * AK;
        const int ci = k >> 5, j = k & 31;
        row[ci * 64 + j]      = h;
        row[ci * 64 + 32 + j] = lo;
    }
}

// ---------------------------------------------------------------------------
// mma.sync bf16 split GEMM: 256x128 CTA tile, 64x64 warp tiles (4x2 grid).
// 32 real-k per stage (48KB), 3 stages, 1 CTA/SM (8 warps).
// ---------------------------------------------------------------------------
#define NKIT 32               // 1024 real k / 32
#define STG_BYTES 49152       // A 32KB (256 rows) + B 16KB (128 rows)
#define SMEM_MMA (3*STG_BYTES)

template<int QKV>
__global__ __launch_bounds__(256, 1)
void gemm_mma(const __nv_bfloat16* __restrict__ A, const __nv_bfloat16* __restrict__ B,
              const float* __restrict__ bias, float* __restrict__ out0,
              float* __restrict__ present, int N,
              __nv_bfloat16* __restrict__ qsp, __nv_bfloat16* __restrict__ ksp,
              __nv_bfloat16* __restrict__ vsp)
{
    extern __shared__ __align__(128) char smem[];
    const uint32_t sbase = smem_u32(smem);

    const int tid  = threadIdx.x;
    const int lane = tid & 31, wid = tid >> 5;
    const int m0 = blockIdx.y * 256, n0 = blockIdx.x * 128;
    const int wm0 = (wid >> 1) * 64;      // warp m offset (0..192)
    const int wn0 = (wid & 1) * 64;       // warp n offset (0 or 64)

    // Loader: 8 threads per row (8 x 16B = 128B row), 1 chunk per row.
    const int lr = tid >> 3;              // 0..31
    const int lc = tid & 7;               // 0..7
    const uint32_t swOff = (uint32_t)((lc ^ (lr & 7)) << 4);
    const __nv_bfloat16* aB = A + (size_t)(m0 + lr) * AK + lc * 8;
    const __nv_bfloat16* bB = B + (size_t)(n0 + lr) * AK + lc * 8;

    float c[4][8][4];
#pragma unroll
    for (int mi = 0; mi < 4; mi++)
#pragma unroll
        for (int ni = 0; ni < 8; ni++)
#pragma unroll
            for (int e = 0; e < 4; e++) c[mi][ni][e] = 0.f;

    auto load_stage = [&](int st, int kt) {
        const uint32_t s0 = sbase + st * STG_BYTES;
        const __nv_bfloat16* ag = aB + kt * 64;
        const __nv_bfloat16* bg = bB + kt * 64;
#pragma unroll
        for (int i = 0; i < 8; i++)   // A: rows lr, lr+32, ..., lr+224
            cp_async16(s0 + (uint32_t)(i * 32 + lr) * 128 + swOff,
                       ag + (size_t)i * 32 * AK);
#pragma unroll
        for (int i = 0; i < 4; i++)   // B: rows lr, lr+32, lr+64, lr+96
            cp_async16(s0 + 32768 + (uint32_t)(i * 32 + lr) * 128 + swOff,
                       bg + (size_t)i * 32 * AK);
    };

    auto compute = [&](int st) {
        const uint32_t sA = sbase + st * STG_BYTES;
        const uint32_t sB = sA + 32768;
#pragma unroll
        for (int ks = 0; ks < 2; ks++) {
            uint32_t ahi[4][4], alo[4][4], bhi[8][2], blo[8][2];
            const int ca = ks * 2 + (lane >> 4);
#pragma unroll
            for (int mi = 0; mi < 4; mi++) {
                const int r = wm0 + mi * 16 + (lane & 15);
                ldmx4(sA + r * 128 + ((( ca      ^ (r & 7))) << 4),
                      ahi[mi][0], ahi[mi][1], ahi[mi][2], ahi[mi][3]);
                ldmx4(sA + r * 128 + ((((ca + 4) ^ (r & 7))) << 4),
                      alo[mi][0], alo[mi][1], alo[mi][2], alo[mi][3]);
            }
            const int cb = ks * 2 + ((lane >> 3) & 1);
            const int rbase = wn0 + (lane & 7) + ((lane >> 4) << 3);
#pragma unroll
            for (int np = 0; np < 4; np++) {
                const int r = rbase + np * 16;
                uint32_t r0, r1, r2, r3;
                ldmx4(sB + r * 128 + ((( cb      ^ (r & 7))) << 4), r0, r1, r2, r3);
                bhi[np * 2][0] = r0;     bhi[np * 2][1] = r1;
                bhi[np * 2 + 1][0] = r2; bhi[np * 2 + 1][1] = r3;
                ldmx4(sB + r * 128 + ((((cb + 4) ^ (r & 7))) << 4), r0, r1, r2, r3);
                blo[np * 2][0] = r0;     blo[np * 2][1] = r1;
                blo[np * 2 + 1][0] = r2; blo[np * 2 + 1][1] = r3;
            }
#pragma unroll
            for (int mi = 0; mi < 4; mi++)
#pragma unroll
                for (int ni = 0; ni < 8; ni++)
                    mma_bf16(c[mi][ni], ahi[mi][0], ahi[mi][1], ahi[mi][2], ahi[mi][3],
                             bhi[ni][0], bhi[ni][1]);
#pragma unroll
            for (int mi = 0; mi < 4; mi++)
#pragma unroll
                for (int ni = 0; ni < 8; ni++)
                    mma_bf16(c[mi][ni], ahi[mi][0], ahi[mi][1], ahi[mi][2], ahi[mi][3],
                             blo[ni][0], blo[ni][1]);
#pragma unroll
            for (int mi = 0; mi < 4; mi++)
#pragma unroll
                for (int ni = 0; ni < 8; ni++)
                    mma_bf16(c[mi][ni], alo[mi][0], alo[mi][1], alo[mi][2], alo[mi][3],
                             bhi[ni][0], bhi[ni][1]);
        }
    };

    load_stage(0, 0); CP_COMMIT();
    load_stage(1, 1); CP_COMMIT();

    for (int kt = 0; kt < NKIT; kt++) {
        CP_WAIT(1);
        __syncthreads();
        if (kt + 2 < NKIT) load_stage((kt + 2) % 3, kt + 2);
        CP_COMMIT();
        compute(kt % 3);
    }

    const int gr = lane >> 2, tc = lane & 3;
#pragma unroll
    for (int mi = 0; mi < 4; mi++) {
#pragma unroll
        for (int rr = 0; rr < 2; rr++) {
            const int m = m0 + wm0 + mi * 16 + gr + rr * 8;
            const int bidx = m >> 11, s = m & (SEQ - 1);
#pragma unroll
            for (int ni = 0; ni < 8; ni++) {
                const int n = n0 + wn0 + ni * 8 + tc * 2;
                float2 bb = *(const float2*)(bias + n);
                float2 v;
                v.x = c[mi][ni][rr * 2 + 0] + bb.x;
                v.y = c[mi][ni][rr * 2 + 1] + bb.y;
                if (QKV == 0) {
                    *(float2*)&out0[(size_t)m * N + n] = v;
                } else {
                    const int tsr = n >> 10;           // 0=q 1=k 2=v
                    const int nn  = n & (D_MODEL - 1);
                    const int h   = nn >> 6, d = nn & 63;
                    const size_t rowi = ((size_t)bidx * NHEAD + h) * SEQ + s;
                    if (tsr == 0) {
                        float q0v = v.x * QSCALE, q1v = v.y * QSCALE;
                        float h0, h1;
                        uint32_t hh = pack_hi(q0v, q1v, h0, h1);
                        uint32_t ll = pack_bf2(q0v - h0, q1v - h1);
                        uint32_t* qrow = (uint32_t*)(qsp + rowi * 128);
                        qrow[d >> 1]        = hh;
                        qrow[32 + (d >> 1)] = ll;
                    } else {
                        float* dst = present +
                            ((((size_t)(bidx * 2 + (tsr - 1)) * NHEAD + h) * SEQ + s) * DEPTH + d);
                        *(float2*)dst = v;
                        float h0, h1;
                        uint32_t hh = pack_hi(v.x, v.y, h0, h1);
                        uint32_t ll = pack_bf2(v.x - h0, v.y - h1);
                        uint32_t* krow = (uint32_t*)((tsr == 1 ? ksp : vsp) + rowi * 128);
                        krow[d >> 1]        = hh;
                        krow[32 + (d >> 1)] = ll;
                    }
                }
            }
        }
    }
}

// ---------------------------------------------------------------------------
// Tensor-core flash attention (split-bf16, exact to ~1.5e-5).
// CTA: 256 threads (8 warps), Br=128 (16 q-rows/warp), Bc=64.
// ---------------------------------------------------------------------------
#define ATTN_SMEM (32768 + 2*32768)   // Q 32KB + 2 x (K 16KB + V 16KB)

__global__ __launch_bounds__(256, 1)
void attn_mma(const __nv_bfloat16* __restrict__ qs, const __nv_bfloat16* __restrict__ ks,
              const __nv_bfloat16* __restrict__ vs, __nv_bfloat16* __restrict__ aao)
{
    extern __shared__ __align__(128) char smem[];
    const uint32_t QS = smem_u32(smem);

    const int tid  = threadIdx.x;
    const int lane = tid & 31, wid = tid >> 5;
    const int qt = (int)gridDim.x - 1 - (int)blockIdx.x;   // long tiles first
    const int h  = blockIdx.y, b = blockIdx.z;
    const int q0 = qt * 128;
    const size_t bh = ((size_t)b * NHEAD + h) * SEQ;

    const __nv_bfloat16* qg = qs + (bh + q0) * 128;
    const __nv_bfloat16* kg = ks + bh * 128;
    const __nv_bfloat16* vg = vs + bh * 128;

#pragma unroll
    for (int i = 0; i < 8; i++) {
        int idx = i * 256 + tid;
        int row = idx >> 4, cc = idx & 15;
        cp_async16(QS + row * 256 + ((cc ^ (row & 7)) << 4), qg + row * 128 + cc * 8);
    }
    auto loadKV = [&](int kt, int buf) {
        const uint32_t KB = QS + 32768 + buf * 32768;
        const uint32_t VB = KB + 16384;
        const __nv_bfloat16* kp = kg + (size_t)kt * 64 * 128;
        const __nv_bfloat16* vp = vg + (size_t)kt * 64 * 128;
#pragma unroll
        for (int i = 0; i < 4; i++) {
            int idx = i * 256 + tid;
            int row = idx >> 4, cc = idx & 15;
            uint32_t so = row * 256 + ((cc ^ (row & 7)) << 4);
            cp_async16(KB + so, kp + row * 128 + cc * 8);
            cp_async16(VB + so, vp + row * 128 + cc * 8);
        }
    };
    const int ntiles = 2 * qt + 2;
    loadKV(0, 0); CP_COMMIT();
    loadKV(1, 1); CP_COMMIT();

    float m2[2] = { -1e30f, -1e30f };
    float l2[2] = { 0.f, 0.f };
    float oacc[8][4];
#pragma unroll
    for (int j = 0; j < 8; j++)
#pragma unroll
        for (int e = 0; e < 4; e++) oacc[j][e] = 0.f;

    const int arow = wid * 16 + (lane & 15);

    for (int kt = 0; kt < ntiles; kt++) {
        if (kt + 1 < ntiles) { CP_WAIT(1); } else { CP_WAIT(0); }
        __syncthreads();
        const uint32_t KB = QS + 32768 + (kt & 1) * 32768;
        const uint32_t VB = KB + 16384;

        float sacc[8][4];
#pragma unroll
        for (int j = 0; j < 8; j++)
#pragma unroll
            for (int e = 0; e < 4; e++) sacc[j][e] = 0.f;

#pragma unroll
        for (int s = 0; s < 4; s++) {
            uint32_t ah[4], al[4];
            const int ca = s * 2 + (lane >> 4);
            ldmx4(QS + arow * 256 + (((ca     ) ^ (arow & 7)) << 4), ah[0], ah[1], ah[2], ah[3]);
            ldmx4(QS + arow * 256 + (((ca +  8) ^ (arow & 7)) << 4), al[0], al[1], al[2], al[3]);
            uint32_t bh_[8][2], bl_[8][2];
            const int rb = (lane & 7) + ((lane >> 4) << 3);
            const int cb = s * 2 + ((lane >> 3) & 1);
#pragma unroll
            for (int g = 0; g < 4; g++) {
                const int r = g * 16 + rb;
                uint32_t r0, r1, r2, r3;
                ldmx4(KB + r * 256 + (((cb    ) ^ (r & 7)) << 4), r0, r1, r2, r3);
                bh_[2*g][0] = r0; bh_[2*g][1] = r1; bh_[2*g+1][0] = r2; bh_[2*g+1][1] = r3;
                ldmx4(KB + r * 256 + (((cb + 8) ^ (r & 7)) << 4), r0, r1, r2, r3);
                bl_[2*g][0] = r0; bl_[2*g][1] = r1; bl_[2*g+1][0] = r2; bl_[2*g+1][1] = r3;
            }
#pragma unroll
            for (int j = 0; j < 8; j++) {
                mma_bf16(sacc[j], ah[0], ah[1], ah[2], ah[3], bh_[j][0], bh_[j][1]);
                mma_bf16(sacc[j], ah[0], ah[1], ah[2], ah[3], bl_[j][0], bl_[j][1]);
                mma_bf16(sacc[j], al[0], al[1], al[2], al[3], bh_[j][0], bh_[j][1]);
            }
        }

        if (kt >= 2 * qt) {
            const int k0 = kt * 64;
            const int qr = q0 + wid * 16 + (lane >> 2);
#pragma unroll
            for (int j = 0; j < 8; j++) {
                const int kc = k0 + j * 8 + (lane & 3) * 2;
                if (kc     > qr)     sacc[j][0] = -1e30f;
                if (kc + 1 > qr)     sacc[j][1] = -1e30f;
                if (kc     > qr + 8) sacc[j][2] = -1e30f;
                if (kc + 1 > qr + 8) sacc[j][3] = -1e30f;
            }
        }

        uint32_t phi[8][2], plo[8][2];
#pragma unroll
        for (int hf = 0; hf < 2; hf++) {
            float mx = -1e30f;
#pragma unroll
            for (int j = 0; j < 8; j++)
                mx = fmaxf(mx, fmaxf(sacc[j][hf*2], sacc[j][hf*2+1]));
            mx = fmaxf(mx, __shfl_xor_sync(0xffffffffu, mx, 1));
            mx = fmaxf(mx, __shfl_xor_sync(0xffffffffu, mx, 2));
            const float newm  = fmaxf(m2[hf], mx);
            const float alpha = exp2_poly(m2[hf] - newm);
            float sum = 0.f;
#pragma unroll
            for (int j = 0; j < 8; j++) {
                float p0 = exp2_poly(sacc[j][hf*2]   - newm);
                float p1 = exp2_poly(sacc[j][hf*2+1] - newm);
                sum += p0 + p1;
                float h0, h1;
                phi[j][hf] = pack_hi(p0, p1, h0, h1);
                plo[j][hf] = pack_bf2(p0 - h0, p1 - h1);
            }
            sum += __shfl_xor_sync(0xffffffffu, sum, 1);
            sum += __shfl_xor_sync(0xffffffffu, sum, 2);
            l2[hf] = l2[hf] * alpha + sum;
            m2[hf] = newm;
#pragma unroll
            for (int j = 0; j < 8; j++) {
                oacc[j][hf*2]   *= alpha;
                oacc[j][hf*2+1] *= alpha;
            }
        }

#pragma unroll
        for (int s = 0; s < 4; s++) {
            uint32_t pah[4] = { phi[2*s][0], phi[2*s][1], phi[2*s+1][0], phi[2*s+1][1] };
            uint32_t pal[4] = { plo[2*s][0], plo[2*s][1], plo[2*s+1][0], plo[2*s+1][1] };
            const int rv = s * 16 + (lane & 15);
            uint32_t bvh[8][2], bvl[8][2];
#pragma unroll
            for (int np = 0; np < 4; np++) {
                const int cv = np * 2 + (lane >> 4);
                uint32_t r0, r1, r2, r3;
                ldmx4t(VB + rv * 256 + (((cv    ) ^ (rv & 7)) << 4), r0, r1, r2, r3);
                bvh[2*np][0] = r0; bvh[2*np][1] = r1; bvh[2*np+1][0] = r2; bvh[2*np+1][1] = r3;
                ldmx4t(VB + rv * 256 + (((cv + 8) ^ (rv & 7)) << 4), r0, r1, r2, r3);
                bvl[2*np][0] = r0; bvl[2*np][1] = r1; bvl[2*np+1][0] = r2; bvl[2*np+1][1] = r3;
            }
#pragma unroll
            for (int j = 0; j < 8; j++) {
                mma_bf16(oacc[j], pah[0], pah[1], pah[2], pah[3], bvh[j][0], bvh[j][1]);
                mma_bf16(oacc[j], pah[0], pah[1], pah[2], pah[3], bvl[j][0], bvl[j][1]);
                mma_bf16(oacc[j], pal[0], pal[1], pal[2], pal[3], bvh[j][0], bvh[j][1]);
            }
        }

        __syncthreads();
        if (kt + 2 < ntiles) loadKV(kt + 2, kt & 1);
        CP_COMMIT();
    }

    // epilogue: write proj input in dedup layout [m][chunk32][hi32|lo32]
    const float inv0 = 1.f / l2[0], inv1 = 1.f / l2[1];
    const int r = lane >> 2, cp2 = (lane & 3) * 2;
#pragma unroll
    for (int j = 0; j < 8; j++) {
        const int col = h * 64 + j * 8 + cp2;
        const int ci = col >> 5, jj = col & 31;
#pragma unroll
        for (int hf = 0; hf < 2; hf++) {
            const float inv = hf ? inv1 : inv0;
            const int m = b * SEQ + q0 + wid * 16 + r + hf * 8;
            const float v0 = oacc[j][hf*2]   * inv;
            const float v1 = oacc[j][hf*2+1] * inv;
            float h0, h1;
            uint32_t hh = pack_hi(v0, v1, h0, h1);
            uint32_t ll = pack_bf2(v0 - h0, v1 - h1);
            uint32_t* row = (uint32_t*)(aao + (size_t)m * AK);
            row[ci * 32 + (jj >> 1)]      = hh;
            row[ci * 32 + 16 + (jj >> 1)] = ll;
        }
    }
}

// ---------------------------------------------------------------------------
extern "C" void kernel_launch(void* const* d_in, const int* in_sizes, int n_in,
                              void* d_out, int out_size)
{
    const float* x      = (const float*)d_in[0];
    const float* w_attn = (const float*)d_in[2];
    const float* b_attn = (const float*)d_in[3];
    const float* w_proj = (const float*)d_in[4];
    const float* b_proj = (const float*)d_in[5];

    float* out     = (float*)d_out;
    float* present = out + (size_t)M_TOTAL * D_MODEL;

    __nv_bfloat16 *gAx, *gAao, *gBq, *gBp, *gqs, *gks, *gvs;
    cudaGetSymbolAddress((void**)&gAx,  g_Ax);
    cudaGetSymbolAddress((void**)&gAao, g_Aao);
    cudaGetSymbolAddress((void**)&gBq,  g_Bqkv);
    cudaGetSymbolAddress((void**)&gBp,  g_Bprj);
    cudaGetSymbolAddress((void**)&gqs,  g_qs);
    cudaGetSymbolAddress((void**)&gks,  g_ks);
    cudaGetSymbolAddress((void**)&gvs,  g_vs);

    static bool attr_set = false;
    if (!attr_set) {
        cudaFuncSetAttribute(attn_mma,    cudaFuncAttributeMaxDynamicSharedMemorySize, ATTN_SMEM);
        cudaFuncSetAttribute(gemm_mma<1>, cudaFuncAttributeMaxDynamicSharedMemorySize, SMEM_MMA);
        cudaFuncSetAttribute(gemm_mma<0>, cudaFuncAttributeMaxDynamicSharedMemorySize, SMEM_MMA);
        attr_set = true;
    }

    // Prep: split-bf16 operands (dedup layout)
    conv_a_kernel<<<(M_TOTAL * 256 + 255) / 256, 256>>>(x, gAx);
    conv_w_kernel<<<dim3(3 * D_MODEL / 32, D_MODEL / 32), dim3(32, 8)>>>(w_attn, gBq, 3 * D_MODEL);
    conv_w_kernel<<<dim3(D_MODEL / 32, D_MODEL / 32), dim3(32, 8)>>>(w_proj, gBp, D_MODEL);

    // QKV GEMM with fused split/scale scatter epilogue
    gemm_mma<1><<<dim3(3 * D_MODEL / 128, M_TOTAL / 256), 256, SMEM_MMA>>>(
        gAx, gBq, b_attn, nullptr, present, 3 * D_MODEL, gqs, gks, gvs);

    // Tensor-core flash attention -> writes split proj input directly
    attn_mma<<<dim3(SEQ / 128, NHEAD, BATCH), 256, ATTN_SMEM>>>(gqs, gks, gvs, gAao);

    // Proj GEMM
    gemm_mma<0><<<dim3(D_MODEL / 128, M_TOTAL / 256), 256, SMEM_MMA>>>(
        gAao, gBp, b_proj, out, nullptr, D_MODEL, nullptr, nullptr, nullptr);
}

// round 9
// speedup vs baseline: 3.1926x; 1.0285x over previous
#include <cuda_runtime.h>
#include <cuda_bf16.h>
#include <math_constants.h>
#include <cstdint>

// Problem constants
#define D_MODEL 1024
#define NHEAD   16
#define DEPTH   64
#define BATCH   2
#define SEQ     2048
#define M_TOTAL (BATCH*SEQ)   // 4096
#define AK      2048          // dedup split layout: [row][32 chunks][hi32|lo32]
#define QSCALE  (0.125f * 1.4426950408889634f)   // 1/sqrt(64) * log2(e)

// ---------------------------------------------------------------------------
// Scratch (device globals — no allocation allowed)
// ---------------------------------------------------------------------------
__device__ __nv_bfloat16 g_qs [(size_t)BATCH*NHEAD*SEQ*128];  // q split, pre-scaled
__device__ __nv_bfloat16 g_ks [(size_t)BATCH*NHEAD*SEQ*128];  // k split
__device__ __nv_bfloat16 g_vs [(size_t)BATCH*NHEAD*SEQ*128];  // v split
__device__ __nv_bfloat16 g_Ax [(size_t)M_TOTAL*AK];           // x split
__device__ __nv_bfloat16 g_Aao[(size_t)M_TOTAL*AK];           // attn-out split
__device__ __nv_bfloat16 g_Bqkv[(size_t)3*D_MODEL*AK];        // w_attn^T split
__device__ __nv_bfloat16 g_Bprj[(size_t)D_MODEL*AK];          // w_proj^T split

// ---------------------------------------------------------------------------
// Helpers
// ---------------------------------------------------------------------------
__device__ __forceinline__ uint32_t smem_u32(const void* p) {
    uint32_t a;
    asm("{ .reg .u64 t; cvta.to.shared.u64 t, %1; cvt.u32.u64 %0, t; }" : "=r"(a) : "l"(p));
    return a;
}
__device__ __forceinline__ void cp_async16(uint32_t saddr, const void* gptr) {
    asm volatile("cp.async.cg.shared.global [%0], [%1], 16;" :: "r"(saddr), "l"(gptr));
}
#define CP_COMMIT() asm volatile("cp.async.commit_group;" ::: "memory")
#define CP_WAIT(n)  asm volatile("cp.async.wait_group %0;" :: "n"(n) : "memory")

__device__ __forceinline__ void ldmx4(uint32_t addr, uint32_t& r0, uint32_t& r1,
                                      uint32_t& r2, uint32_t& r3) {
    asm volatile("ldmatrix.sync.aligned.m8n8.x4.shared.b16 {%0,%1,%2,%3}, [%4];"
                 : "=r"(r0), "=r"(r1), "=r"(r2), "=r"(r3) : "r"(addr));
}
__device__ __forceinline__ void ldmx4t(uint32_t addr, uint32_t& r0, uint32_t& r1,
                                       uint32_t& r2, uint32_t& r3) {
    asm volatile("ldmatrix.sync.aligned.m8n8.x4.trans.shared.b16 {%0,%1,%2,%3}, [%4];"
                 : "=r"(r0), "=r"(r1), "=r"(r2), "=r"(r3) : "r"(addr));
}
__device__ __forceinline__ void mma_bf16(float c[4], uint32_t a0, uint32_t a1,
                                         uint32_t a2, uint32_t a3,
                                         uint32_t b0, uint32_t b1) {
    asm volatile("mma.sync.aligned.m16n8k16.row.col.f32.bf16.bf16.f32 "
                 "{%0,%1,%2,%3}, {%4,%5,%6,%7}, {%8,%9}, {%0,%1,%2,%3};"
                 : "+f"(c[0]), "+f"(c[1]), "+f"(c[2]), "+f"(c[3])
                 : "r"(a0), "r"(a1), "r"(a2), "r"(a3), "r"(b0), "r"(b1));
}

// Conversion-free exp2: magic-constant round + deg-6 poly + integer exp add.
// Valid for t <= ~0 (clamped at -125). All ops on 4-cycle fixed pipes.
__device__ __forceinline__ float exp2_fast(float t) {
    t = fmaxf(t, -125.0f);
    float z = t + 12582912.0f;              // 1.5 * 2^23: round-to-nearest int
    float f = t - (z - 12582912.0f);        // f in [-0.5, 0.5]
    float p = 1.535336188319500e-4f;
    p = fmaf(p, f, 1.339887440266574e-3f);
    p = fmaf(p, f, 9.618437357674640e-3f);
    p = fmaf(p, f, 5.550332471162809e-2f);
    p = fmaf(p, f, 2.402264791363012e-1f);
    p = fmaf(p, f, 6.931472028550421e-1f);
    float r = fmaf(p, f, 1.0f);             // 2^f
    return __int_as_float(__float_as_int(r) + (__float_as_int(z) << 23));
}

__device__ __forceinline__ uint32_t pack_hi(float a, float b, float& ha, float& hb) {
    __nv_bfloat162 hh = __floats2bfloat162_rn(a, b);
    ha = __bfloat162float(hh.x);
    hb = __bfloat162float(hh.y);
    return *(uint32_t*)&hh;
}
__device__ __forceinline__ uint32_t pack_bf2(float a, float b) {
    __nv_bfloat162 hh = __floats2bfloat162_rn(a, b);
    return *(uint32_t*)&hh;
}

// ---------------------------------------------------------------------------
// Prep: x[M,1024] fp32 -> A''[M,2048]: per 32-k chunk, [hi32|lo32]
// ---------------------------------------------------------------------------
__global__ __launch_bounds__(256)
void conv_a_kernel(const float* __restrict__ X, __nv_bfloat16* __restrict__ Ad) {
    int i = blockIdx.x * blockDim.x + threadIdx.x;
    if (i >= M_TOTAL * 256) return;
    int m  = i >> 8;
    int kq = (i & 255) << 2;
    float4 v = ((const float4*)X)[i];
    union { __nv_bfloat16 h[4]; uint2 u; } hi, lo;
    hi.h[0] = __float2bfloat16(v.x); lo.h[0] = __float2bfloat16(v.x - __bfloat162float(hi.h[0]));
    hi.h[1] = __float2bfloat16(v.y); lo.h[1] = __float2bfloat16(v.y - __bfloat162float(hi.h[1]));
    hi.h[2] = __float2bfloat16(v.z); lo.h[2] = __float2bfloat16(v.z - __bfloat162float(hi.h[2]));
    hi.h[3] = __float2bfloat16(v.w); lo.h[3] = __float2bfloat16(v.w - __bfloat162float(hi.h[3]));
    const int ci = kq >> 5, j = kq & 31;
    size_t base = (size_t)m * AK + ci * 64 + j;
    *(uint2*)(Ad + base)      = hi.u;
    *(uint2*)(Ad + base + 32) = lo.u;
}

// ---------------------------------------------------------------------------
// Prep: w[1024,N] fp32 -> B''[N,2048] (transposed; chunk layout [hi32|lo32])
// ---------------------------------------------------------------------------
__global__ __launch_bounds__(256)
void conv_w_kernel(const float* __restrict__ W, __nv_bfloat16* __restrict__ Bd, int N) {
    __shared__ float t[32][33];
    const int k0 = blockIdx.y * 32, n0 = blockIdx.x * 32;
    for (int r = threadIdx.y; r < 32; r += 8)
        t[r][threadIdx.x] = W[(size_t)(k0 + r) * N + n0 + threadIdx.x];
    __syncthreads();
    for (int r = threadIdx.y; r < 32; r += 8) {
        const int n = n0 + r, k = k0 + threadIdx.x;
        float v = t[threadIdx.x][r];
        __nv_bfloat16 h  = __float2bfloat16(v);
        __nv_bfloat16 lo = __float2bfloat16(v - __bfloat162float(h));
        __nv_bfloat16* row = Bd + (size_t)n * AK;
        const int ci = k >> 5, j = k & 31;
        row[ci * 64 + j]      = h;
        row[ci * 64 + 32 + j] = lo;
    }
}

// ---------------------------------------------------------------------------
// mma.sync bf16 split GEMM: 256x128 CTA tile, 64x64 warp tiles (4x2 grid).
// 32 real-k per stage (48KB), 3 stages, 1 CTA/SM (8 warps).
// ---------------------------------------------------------------------------
#define NKIT 32               // 1024 real k / 32
#define STG_BYTES 49152       // A 32KB (256 rows) + B 16KB (128 rows)
#define SMEM_MMA (3*STG_BYTES)

template<int QKV>
__global__ __launch_bounds__(256, 1)
void gemm_mma(const __nv_bfloat16* __restrict__ A, const __nv_bfloat16* __restrict__ B,
              const float* __restrict__ bias, float* __restrict__ out0,
              float* __restrict__ present, int N,
              __nv_bfloat16* __restrict__ qsp, __nv_bfloat16* __restrict__ ksp,
              __nv_bfloat16* __restrict__ vsp)
{
    extern __shared__ __align__(128) char smem[];
    const uint32_t sbase = smem_u32(smem);

    const int tid  = threadIdx.x;
    const int lane = tid & 31, wid = tid >> 5;
    const int m0 = blockIdx.y * 256, n0 = blockIdx.x * 128;
    const int wm0 = (wid >> 1) * 64;
    const int wn0 = (wid & 1) * 64;

    const int lr = tid >> 3;
    const int lc = tid & 7;
    const uint32_t swOff = (uint32_t)((lc ^ (lr & 7)) << 4);
    const __nv_bfloat16* aB = A + (size_t)(m0 + lr) * AK + lc * 8;
    const __nv_bfloat16* bB = B + (size_t)(n0 + lr) * AK + lc * 8;

    float c[4][8][4];
#pragma unroll
    for (int mi = 0; mi < 4; mi++)
#pragma unroll
        for (int ni = 0; ni < 8; ni++)
#pragma unroll
            for (int e = 0; e < 4; e++) c[mi][ni][e] = 0.f;

    auto load_stage = [&](int st, int kt) {
        const uint32_t s0 = sbase + st * STG_BYTES;
        const __nv_bfloat16* ag = aB + kt * 64;
        const __nv_bfloat16* bg = bB + kt * 64;
#pragma unroll
        for (int i = 0; i < 8; i++)
            cp_async16(s0 + (uint32_t)(i * 32 + lr) * 128 + swOff,
                       ag + (size_t)i * 32 * AK);
#pragma unroll
        for (int i = 0; i < 4; i++)
            cp_async16(s0 + 32768 + (uint32_t)(i * 32 + lr) * 128 + swOff,
                       bg + (size_t)i * 32 * AK);
    };

    auto compute = [&](int st) {
        const uint32_t sA = sbase + st * STG_BYTES;
        const uint32_t sB = sA + 32768;
#pragma unroll
        for (int ks = 0; ks < 2; ks++) {
            uint32_t ahi[4][4], alo[4][4], bhi[8][2], blo[8][2];
            const int ca = ks * 2 + (lane >> 4);
#pragma unroll
            for (int mi = 0; mi < 4; mi++) {
                const int r = wm0 + mi * 16 + (lane & 15);
                ldmx4(sA + r * 128 + ((( ca      ^ (r & 7))) << 4),
                      ahi[mi][0], ahi[mi][1], ahi[mi][2], ahi[mi][3]);
                ldmx4(sA + r * 128 + ((((ca + 4) ^ (r & 7))) << 4),
                      alo[mi][0], alo[mi][1], alo[mi][2], alo[mi][3]);
            }
            const int cb = ks * 2 + ((lane >> 3) & 1);
            const int rbase = wn0 + (lane & 7) + ((lane >> 4) << 3);
#pragma unroll
            for (int np = 0; np < 4; np++) {
                const int r = rbase + np * 16;
                uint32_t r0, r1, r2, r3;
                ldmx4(sB + r * 128 + ((( cb      ^ (r & 7))) << 4), r0, r1, r2, r3);
                bhi[np * 2][0] = r0;     bhi[np * 2][1] = r1;
                bhi[np * 2 + 1][0] = r2; bhi[np * 2 + 1][1] = r3;
                ldmx4(sB + r * 128 + ((((cb + 4) ^ (r & 7))) << 4), r0, r1, r2, r3);
                blo[np * 2][0] = r0;     blo[np * 2][1] = r1;
                blo[np * 2 + 1][0] = r2; blo[np * 2 + 1][1] = r3;
            }
#pragma unroll
            for (int mi = 0; mi < 4; mi++)
#pragma unroll
                for (int ni = 0; ni < 8; ni++)
                    mma_bf16(c[mi][ni], ahi[mi][0], ahi[mi][1], ahi[mi][2], ahi[mi][3],
                             bhi[ni][0], bhi[ni][1]);
#pragma unroll
            for (int mi = 0; mi < 4; mi++)
#pragma unroll
                for (int ni = 0; ni < 8; ni++)
                    mma_bf16(c[mi][ni], ahi[mi][0], ahi[mi][1], ahi[mi][2], ahi[mi][3],
                             blo[ni][0], blo[ni][1]);
#pragma unroll
            for (int mi = 0; mi < 4; mi++)
#pragma unroll
                for (int ni = 0; ni < 8; ni++)
                    mma_bf16(c[mi][ni], alo[mi][0], alo[mi][1], alo[mi][2], alo[mi][3],
                             bhi[ni][0], bhi[ni][1]);
        }
    };

    load_stage(0, 0); CP_COMMIT();
    load_stage(1, 1); CP_COMMIT();

    for (int kt = 0; kt < NKIT; kt++) {
        CP_WAIT(1);
        __syncthreads();
        if (kt + 2 < NKIT) load_stage((kt + 2) % 3, kt + 2);
        CP_COMMIT();
        compute(kt % 3);
    }

    const int gr = lane >> 2, tc = lane & 3;
#pragma unroll
    for (int mi = 0; mi < 4; mi++) {
#pragma unroll
        for (int rr = 0; rr < 2; rr++) {
            const int m = m0 + wm0 + mi * 16 + gr + rr * 8;
            const int bidx = m >> 11, s = m & (SEQ - 1);
#pragma unroll
            for (int ni = 0; ni < 8; ni++) {
                const int n = n0 + wn0 + ni * 8 + tc * 2;
                float2 bb = *(const float2*)(bias + n);
                float2 v;
                v.x = c[mi][ni][rr * 2 + 0] + bb.x;
                v.y = c[mi][ni][rr * 2 + 1] + bb.y;
                if (QKV == 0) {
                    *(float2*)&out0[(size_t)m * N + n] = v;
                } else {
                    const int tsr = n >> 10;           // 0=q 1=k 2=v
                    const int nn  = n & (D_MODEL - 1);
                    const int h   = nn >> 6, d = nn & 63;
                    const size_t rowi = ((size_t)bidx * NHEAD + h) * SEQ + s;
                    if (tsr == 0) {
                        float q0v = v.x * QSCALE, q1v = v.y * QSCALE;
                        float h0, h1;
                        uint32_t hh = pack_hi(q0v, q1v, h0, h1);
                        uint32_t ll = pack_bf2(q0v - h0, q1v - h1);
                        uint32_t* qrow = (uint32_t*)(qsp + rowi * 128);
                        qrow[d >> 1]        = hh;
                        qrow[32 + (d >> 1)] = ll;
                    } else {
                        float* dst = present +
                            ((((size_t)(bidx * 2 + (tsr - 1)) * NHEAD + h) * SEQ + s) * DEPTH + d);
                        *(float2*)dst = v;
                        float h0, h1;
                        uint32_t hh = pack_hi(v.x, v.y, h0, h1);
                        uint32_t ll = pack_bf2(v.x - h0, v.y - h1);
                        uint32_t* krow = (uint32_t*)((tsr == 1 ? ksp : vsp) + rowi * 128);
                        krow[d >> 1]        = hh;
                        krow[32 + (d >> 1)] = ll;
                    }
                }
            }
        }
    }
}

// ---------------------------------------------------------------------------
// Tensor-core flash attention (split-bf16). Br=128, Bc=128.
// 256 threads (8 warps, 16 q-rows each). P packed in place into sacc.
// ---------------------------------------------------------------------------
#define ATTN_SMEM (32768 + 2*65536)   // Q 32KB + 2 x (K 32KB + V 32KB)

__global__ __launch_bounds__(256, 1)
void attn_mma(const __nv_bfloat16* __restrict__ qs, const __nv_bfloat16* __restrict__ ks,
              const __nv_bfloat16* __restrict__ vs, __nv_bfloat16* __restrict__ aao)
{
    extern __shared__ __align__(128) char smem[];
    const uint32_t QS = smem_u32(smem);

    const int tid  = threadIdx.x;
    const int lane = tid & 31, wid = tid >> 5;
    const int qt = (int)gridDim.x - 1 - (int)blockIdx.x;   // long tiles first
    const int h  = blockIdx.y, b = blockIdx.z;
    const int q0 = qt * 128;
    const size_t bh = ((size_t)b * NHEAD + h) * SEQ;

    const __nv_bfloat16* qg = qs + (bh + q0) * 128;
    const __nv_bfloat16* kg = ks + bh * 128;
    const __nv_bfloat16* vg = vs + bh * 128;

#pragma unroll
    for (int i = 0; i < 8; i++) {
        int idx = i * 256 + tid;
        int row = idx >> 4, cc = idx & 15;
        cp_async16(QS + row * 256 + ((cc ^ (row & 7)) << 4), qg + row * 128 + cc * 8);
    }
    auto loadKV = [&](int kt, int buf) {
        const uint32_t KB = QS + 32768 + buf * 65536;
        const uint32_t VB = KB + 32768;
        const __nv_bfloat16* kp = kg + (size_t)kt * 128 * 128;
        const __nv_bfloat16* vp = vg + (size_t)kt * 128 * 128;
#pragma unroll
        for (int i = 0; i < 8; i++) {
            int idx = i * 256 + tid;
            int row = idx >> 4, cc = idx & 15;
            uint32_t so = row * 256 + ((cc ^ (row & 7)) << 4);
            cp_async16(KB + so, kp + row * 128 + cc * 8);
            cp_async16(VB + so, vp + row * 128 + cc * 8);
        }
    };
    const int ntiles = qt + 1;
    loadKV(0, 0); CP_COMMIT();
    loadKV(ntiles > 1 ? 1 : 0, 1); CP_COMMIT();

    float m2[2] = { -1e30f, -1e30f };
    float l2[2] = { 0.f, 0.f };
    float oacc[8][4];
#pragma unroll
    for (int j = 0; j < 8; j++)
#pragma unroll
        for (int e = 0; e < 4; e++) oacc[j][e] = 0.f;

    const int arow = wid * 16 + (lane & 15);

    for (int kt = 0; kt < ntiles; kt++) {
        if (kt + 1 < ntiles) { CP_WAIT(1); } else { CP_WAIT(0); }
        __syncthreads();
        const uint32_t KB = QS + 32768 + (kt & 1) * 65536;
        const uint32_t VB = KB + 32768;

        // ---- S = Q''·K''^T over 128x128 tile; sacc[j] = n-chunk j (8 cols) ----
        float sacc[16][4];
#pragma unroll
        for (int j = 0; j < 16; j++)
#pragma unroll
            for (int e = 0; e < 4; e++) sacc[j][e] = 0.f;

#pragma unroll
        for (int s = 0; s < 4; s++) {
            uint32_t ah[4], al[4];
            const int ca = s * 2 + (lane >> 4);
            ldmx4(QS + arow * 256 + (((ca     ) ^ (arow & 7)) << 4), ah[0], ah[1], ah[2], ah[3]);
            ldmx4(QS + arow * 256 + (((ca +  8) ^ (arow & 7)) << 4), al[0], al[1], al[2], al[3]);
            const int rb = (lane & 7) + ((lane >> 4) << 3);
            const int cb = s * 2 + ((lane >> 3) & 1);
#pragma unroll
            for (int half = 0; half < 2; half++) {
                uint32_t bh_[8][2], bl_[8][2];
#pragma unroll
                for (int g = 0; g < 4; g++) {
                    const int r = (half * 4 + g) * 16 + rb;
                    uint32_t r0, r1, r2, r3;
                    ldmx4(KB + r * 256 + (((cb    ) ^ (r & 7)) << 4), r0, r1, r2, r3);
                    bh_[2*g][0] = r0; bh_[2*g][1] = r1; bh_[2*g+1][0] = r2; bh_[2*g+1][1] = r3;
                    ldmx4(KB + r * 256 + (((cb + 8) ^ (r & 7)) << 4), r0, r1, r2, r3);
                    bl_[2*g][0] = r0; bl_[2*g][1] = r1; bl_[2*g+1][0] = r2; bl_[2*g+1][1] = r3;
                }
#pragma unroll
                for (int jj = 0; jj < 8; jj++) {
                    float* sc = sacc[half * 8 + jj];
                    mma_bf16(sc, ah[0], ah[1], ah[2], ah[3], bh_[jj][0], bh_[jj][1]);
                    mma_bf16(sc, ah[0], ah[1], ah[2], ah[3], bl_[jj][0], bl_[jj][1]);
                    mma_bf16(sc, al[0], al[1], al[2], al[3], bh_[jj][0], bh_[jj][1]);
                }
            }
        }

        // ---- causal mask (only the diagonal tile) ----
        if (kt == qt) {
            const int k0 = kt * 128;
            const int qr = q0 + wid * 16 + (lane >> 2);
#pragma unroll
            for (int j = 0; j < 16; j++) {
                const int kc = k0 + j * 8 + (lane & 3) * 2;
                if (kc     > qr)     sacc[j][0] = -1e30f;
                if (kc + 1 > qr)     sacc[j][1] = -1e30f;
                if (kc     > qr + 8) sacc[j][2] = -1e30f;
                if (kc + 1 > qr + 8) sacc[j][3] = -1e30f;
            }
        }

        // ---- online softmax; pack split-P in place into sacc ----
#pragma unroll
        for (int hf = 0; hf < 2; hf++) {
            float mx = -1e30f;
#pragma unroll
            for (int j = 0; j < 16; j++)
                mx = fmaxf(mx, fmaxf(sacc[j][hf*2], sacc[j][hf*2+1]));
            mx = fmaxf(mx, __shfl_xor_sync(0xffffffffu, mx, 1));
            mx = fmaxf(mx, __shfl_xor_sync(0xffffffffu, mx, 2));
            const float newm  = fmaxf(m2[hf], mx);
            const float alpha = exp2_fast(m2[hf] - newm);
            float sum = 0.f;
#pragma unroll
            for (int j = 0; j < 16; j++) {
                float p0 = exp2_fast(sacc[j][hf*2]   - newm);
                float p1 = exp2_fast(sacc[j][hf*2+1] - newm);
                sum += p0 + p1;
                float h0, h1;
                uint32_t hh = pack_hi(p0, p1, h0, h1);
                uint32_t ll = pack_bf2(p0 - h0, p1 - h1);
                sacc[j][hf*2]   = __uint_as_float(hh);
                sacc[j][hf*2+1] = __uint_as_float(ll);
            }
            sum += __shfl_xor_sync(0xffffffffu, sum, 1);
            sum += __shfl_xor_sync(0xffffffffu, sum, 2);
            l2[hf] = l2[hf] * alpha + sum;
            m2[hf] = newm;
#pragma unroll
            for (int j = 0; j < 8; j++) {
                oacc[j][hf*2]   *= alpha;
                oacc[j][hf*2+1] *= alpha;
            }
        }

        // ---- O += P''·V'' over 128 k ----
#pragma unroll
        for (int s = 0; s < 8; s++) {
            uint32_t pah[4] = { __float_as_uint(sacc[2*s][0]),   __float_as_uint(sacc[2*s][2]),
                                __float_as_uint(sacc[2*s+1][0]), __float_as_uint(sacc[2*s+1][2]) };
            uint32_t pal[4] = { __float_as_uint(sacc[2*s][1]),   __float_as_uint(sacc[2*s][3]),
                                __float_as_uint(sacc[2*s+1][1]), __float_as_uint(sacc[2*s+1][3]) };
            const int rv = s * 16 + (lane & 15);
            uint32_t bvh[8][2], bvl[8][2];
#pragma unroll
            for (int np = 0; np < 4; np++) {
                const int cv = np * 2 + (lane >> 4);
                uint32_t r0, r1, r2, r3;
                ldmx4t(VB + rv * 256 + (((cv    ) ^ (rv & 7)) << 4), r0, r1, r2, r3);
                bvh[2*np][0] = r0; bvh[2*np][1] = r1; bvh[2*np+1][0] = r2; bvh[2*np+1][1] = r3;
                ldmx4t(VB + rv * 256 + (((cv + 8) ^ (rv & 7)) << 4), r0, r1, r2, r3);
                bvl[2*np][0] = r0; bvl[2*np][1] = r1; bvl[2*np+1][0] = r2; bvl[2*np+1][1] = r3;
            }
#pragma unroll
            for (int j = 0; j < 8; j++) {
                mma_bf16(oacc[j], pah[0], pah[1], pah[2], pah[3], bvh[j][0], bvh[j][1]);
                mma_bf16(oacc[j], pah[0], pah[1], pah[2], pah[3], bvl[j][0], bvl[j][1]);
                mma_bf16(oacc[j], pal[0], pal[1], pal[2], pal[3], bvh[j][0], bvh[j][1]);
            }
        }

        __syncthreads();
        if (kt + 2 < ntiles) { loadKV(kt + 2, kt & 1); }
        CP_COMMIT();
    }

    // epilogue: write proj input in dedup layout [m][chunk32][hi32|lo32]
    const float inv0 = 1.f / l2[0], inv1 = 1.f / l2[1];
    const int r = lane >> 2, cp2 = (lane & 3) * 2;
#pragma unroll
    for (int j = 0; j < 8; j++) {
        const int col = h * 64 + j * 8 + cp2;
        const int ci = col >> 5, jj = col & 31;
#pragma unroll
        for (int hf = 0; hf < 2; hf++) {
            const float inv = hf ? inv1 : inv0;
            const int m = b * SEQ + q0 + wid * 16 + r + hf * 8;
            const float v0 = oacc[j][hf*2]   * inv;
            const float v1 = oacc[j][hf*2+1] * inv;
            float h0, h1;
            uint32_t hh = pack_hi(v0, v1, h0, h1);
            uint32_t ll = pack_bf2(v0 - h0, v1 - h1);
            uint32_t* row = (uint32_t*)(aao + (size_t)m * AK);
            row[ci * 32 + (jj >> 1)]      = hh;
            row[ci * 32 + 16 + (jj >> 1)] = ll;
        }
    }
}

// ---------------------------------------------------------------------------
extern "C" void kernel_launch(void* const* d_in, const int* in_sizes, int n_in,
                              void* d_out, int out_size)
{
    const float* x      = (const float*)d_in[0];
    const float* w_attn = (const float*)d_in[2];
    const float* b_attn = (const float*)d_in[3];
    const float* w_proj = (const float*)d_in[4];
    const float* b_proj = (const float*)d_in[5];

    float* out     = (float*)d_out;
    float* present = out + (size_t)M_TOTAL * D_MODEL;

    __nv_bfloat16 *gAx, *gAao, *gBq, *gBp, *gqs, *gks, *gvs;
    cudaGetSymbolAddress((void**)&gAx,  g_Ax);
    cudaGetSymbolAddress((void**)&gAao, g_Aao);
    cudaGetSymbolAddress((void**)&gBq,  g_Bqkv);
    cudaGetSymbolAddress((void**)&gBp,  g_Bprj);
    cudaGetSymbolAddress((void**)&gqs,  g_qs);
    cudaGetSymbolAddress((void**)&gks,  g_ks);
    cudaGetSymbolAddress((void**)&gvs,  g_vs);

    static bool attr_set = false;
    if (!attr_set) {
        cudaFuncSetAttribute(attn_mma,    cudaFuncAttributeMaxDynamicSharedMemorySize, ATTN_SMEM);
        cudaFuncSetAttribute(gemm_mma<1>, cudaFuncAttributeMaxDynamicSharedMemorySize, SMEM_MMA);
        cudaFuncSetAttribute(gemm_mma<0>, cudaFuncAttributeMaxDynamicSharedMemorySize, SMEM_MMA);
        attr_set = true;
    }

    // Prep: split-bf16 operands (dedup layout)
    conv_a_kernel<<<(M_TOTAL * 256 + 255) / 256, 256>>>(x, gAx);
    conv_w_kernel<<<dim3(3 * D_MODEL / 32, D_MODEL / 32), dim3(32, 8)>>>(w_attn, gBq, 3 * D_MODEL);
    conv_w_kernel<<<dim3(D_MODEL / 32, D_MODEL / 32), dim3(32, 8)>>>(w_proj, gBp, D_MODEL);

    // QKV GEMM with fused split/scale scatter epilogue
    gemm_mma<1><<<dim3(3 * D_MODEL / 128, M_TOTAL / 256), 256, SMEM_MMA>>>(
        gAx, gBq, b_attn, nullptr, present, 3 * D_MODEL, gqs, gks, gvs);

    // Tensor-core flash attention -> writes split proj input directly
    attn_mma<<<dim3(SEQ / 128, NHEAD, BATCH), 256, ATTN_SMEM>>>(gqs, gks, gvs, gAao);

    // Proj GEMM
    gemm_mma<0><<<dim3(D_MODEL / 128, M_TOTAL / 256), 256, SMEM_MMA>>>(
        gAao, gBp, b_proj, out, nullptr, D_MODEL, nullptr, nullptr, nullptr);
}